// round 2
// baseline (speedup 1.0000x reference)
#include <cuda_runtime.h>
#include <cuda_fp16.h>
#include <cstdint>

// ----------------------------------------------------------------------------
// Problem constants
// ----------------------------------------------------------------------------
#define NPTS   262144
#define KOFF   27
#define CIN    64
#define COUT   64
#define TILE_M 128
#define NTILES (NPTS / TILE_M)   // 2048
#define EPSV   1e-5f

// ----------------------------------------------------------------------------
// Device scratch (static allocations only)
// ----------------------------------------------------------------------------
// Feature table, interleaved per row: [64 fp16 hi | 64 fp16 lo] = 256B/row.
// Extra row at index NPTS is all zeros (missing-neighbor pad).
__device__ __half g_feat[(size_t)(NPTS + 1) * 128];
// Weights, transposed + split: [k][{hi,lo}][co][ci] fp16
__device__ __half g_wt[(size_t)KOFF * 2 * COUT * CIN];
__device__ float  g_conv[(size_t)NPTS * COUT];   // conv output before BN
__device__ float  g_stats[256];                  // [0:64) sum [64:128) sumsq
                                                 // [128:192) scale [192:256) shift

// ----------------------------------------------------------------------------
// Helpers
// ----------------------------------------------------------------------------
__device__ __forceinline__ uint32_t smem_u32(const void* p) {
    uint32_t a;
    asm("{ .reg .u64 t; cvta.to.shared.u64 t, %1; cvt.u32.u64 %0, t; }"
        : "=r"(a) : "l"(p));
    return a;
}

__device__ __forceinline__ void ldsm4(uint32_t* r, uint32_t addr) {
    asm volatile("ldmatrix.sync.aligned.m8n8.x4.shared.b16 {%0,%1,%2,%3}, [%4];"
                 : "=r"(r[0]), "=r"(r[1]), "=r"(r[2]), "=r"(r[3]) : "r"(addr));
}

__device__ __forceinline__ void mma16816(float* c, const uint32_t* a,
                                         uint32_t b0, uint32_t b1) {
    asm volatile(
        "mma.sync.aligned.m16n8k16.row.col.f32.f16.f16.f32 "
        "{%0,%1,%2,%3}, {%4,%5,%6,%7}, {%8,%9}, {%0,%1,%2,%3};"
        : "+f"(c[0]), "+f"(c[1]), "+f"(c[2]), "+f"(c[3])
        : "r"(a[0]), "r"(a[1]), "r"(a[2]), "r"(a[3]), "r"(b0), "r"(b1));
}

// ----------------------------------------------------------------------------
// Kernel 1: features f32 -> fp16 hi/lo interleaved rows; zero pad row
// ----------------------------------------------------------------------------
__global__ void prep_feat_kernel(const float* __restrict__ feat) {
    const int total4 = (NPTS + 1) * 16;          // float4 count
    int i = blockIdx.x * blockDim.x + threadIdx.x;
    if (i >= total4) return;
    float4 v;
    if (i < NPTS * 16) v = ((const float4*)feat)[i];
    else               v = make_float4(0.f, 0.f, 0.f, 0.f);

    __half h0 = __float2half_rn(v.x), h1 = __float2half_rn(v.y);
    __half h2 = __float2half_rn(v.z), h3 = __float2half_rn(v.w);
    __half l0 = __float2half_rn(v.x - __half2float(h0));
    __half l1 = __float2half_rn(v.y - __half2float(h1));
    __half l2 = __float2half_rn(v.z - __half2float(h2));
    __half l3 = __float2half_rn(v.w - __half2float(h3));

    int row = i >> 4, c4 = i & 15;
    __half2* hi = (__half2*)(g_feat + (size_t)row * 128 + c4 * 4);
    __half2* lo = (__half2*)(g_feat + (size_t)row * 128 + 64 + c4 * 4);
    hi[0] = __halves2half2(h0, h1); hi[1] = __halves2half2(h2, h3);
    lo[0] = __halves2half2(l0, l1); lo[1] = __halves2half2(l2, l3);
}

// ----------------------------------------------------------------------------
// Kernel 2: weights [k][ci][co] -> [k][{hi,lo}][co][ci]; zero stats accums
// ----------------------------------------------------------------------------
__global__ void prep_w_kernel(const float* __restrict__ w) {
    int k = blockIdx.x;
    if (k == KOFF) {
        if (threadIdx.x < 128) g_stats[threadIdx.x] = 0.f;
        return;
    }
    for (int idx = threadIdx.x; idx < CIN * COUT; idx += blockDim.x) {
        int ci = idx / COUT, co = idx % COUT;
        float f = w[(size_t)k * CIN * COUT + idx];
        __half hi = __float2half_rn(f);
        __half lo = __float2half_rn(f - __half2float(hi));
        size_t base = (size_t)k * 2 * COUT * CIN;
        g_wt[base + (size_t)co * CIN + ci]              = hi;
        g_wt[base + COUT * CIN + (size_t)co * CIN + ci] = lo;
    }
}

// ----------------------------------------------------------------------------
// Kernel 3: gather + mma.sync conv.  2048 CTAs x 256 threads (8 warps).
// SMEM (144B padded rows, conflict-free ldmatrix):
//   A_hi[128][144B] | A_lo[128][144B] | W_hi[64][144B] | W_lo[64][144B]
// ----------------------------------------------------------------------------
#define ROWB  144
#define A_HI  0
#define A_LO  (128 * ROWB)             // 18432
#define W_HI  (2 * 128 * ROWB)         // 36864
#define W_LO  (W_HI + 64 * ROWB)       // 46080
#define CONV_SMEM (W_LO + 64 * ROWB)   // 55296

__global__ void __launch_bounds__(256, 2) conv_kernel(const int* __restrict__ nbr) {
    extern __shared__ char smem[];
    const uint32_t sb  = smem_u32(smem);
    const int tid  = threadIdx.x;
    const int wid  = tid >> 5;
    const int lane = tid & 31;
    const int row0 = blockIdx.x * TILE_M;

    float c[8][4];
    #pragma unroll
    for (int i = 0; i < 8; i++)
        #pragma unroll
        for (int j = 0; j < 4; j++) c[i][j] = 0.f;

    // Gather assignment: thread t covers row r = t/2, table half = t&1 (hi/lo).
    const int  grow = tid >> 1;
    const int  ghalf = tid & 1;
    const int* idxp = nbr + row0 + grow;
    char*      arow = smem + (ghalf ? A_LO : A_HI) + grow * ROWB;

    // ldmatrix source addresses
    const uint32_t aAddrHi = sb + A_HI + (wid * 16 + (lane & 15)) * ROWB + (lane >> 4) * 16;
    const uint32_t aAddrLo = aAddrHi + (A_LO - A_HI);
    const uint32_t bRow    = (lane & 7) + ((lane >> 4) << 3);
    const uint32_t bOff    = ((lane >> 3) & 1) * 16;
    const uint32_t bAddrHi = sb + W_HI + bRow * ROWB + bOff;
    const uint32_t bAddrLo = bAddrHi + (W_LO - W_HI);

    for (int k = 0; k < KOFF; k++) {
        __syncthreads();   // previous MMA phase done before overwrite

        // --- gather one feature row-half (8 x int4 = 128B contiguous) ---
        int g = __ldg(idxp + k * NPTS);             // 0..NPTS (NPTS = zero row)
        const int4* fr = (const int4*)g_feat + (size_t)g * 16 + ghalf * 8;
        #pragma unroll
        for (int q = 0; q < 8; q++)
            *(int4*)(arow + q * 16) = __ldg(fr + q);

        // --- weights for this k: 1024 int4 (hi 512 | lo 512) ---
        const int4* wsrc = (const int4*)(g_wt + (size_t)k * 2 * COUT * CIN);
        #pragma unroll
        for (int j = 0; j < 4; j++) {
            int lin = tid + j * 256;                // 0..1023
            int rr = (lin & 511) >> 3, qq = lin & 7;
            char* dst = smem + (lin < 512 ? W_HI : W_LO) + rr * ROWB + qq * 16;
            *(int4*)dst = __ldg(wsrc + lin);
        }

        __syncthreads();

        // --- MMA phase: 3-term split, 96 mma/warp ---
        #pragma unroll
        for (int ks = 0; ks < 4; ks++) {
            uint32_t ah[4], al[4];
            ldsm4(ah, aAddrHi + ks * 32);
            ldsm4(al, aAddrLo + ks * 32);
            #pragma unroll
            for (int np = 0; np < 4; np++) {
                uint32_t bh[4], bl[4];
                ldsm4(bh, bAddrHi + np * 16 * ROWB + ks * 32);
                ldsm4(bl, bAddrLo + np * 16 * ROWB + ks * 32);
                mma16816(c[2 * np],     ah, bh[0], bh[1]);
                mma16816(c[2 * np + 1], ah, bh[2], bh[3]);
                mma16816(c[2 * np],     al, bh[0], bh[1]);
                mma16816(c[2 * np + 1], al, bh[2], bh[3]);
                mma16816(c[2 * np],     ah, bl[0], bl[1]);
                mma16816(c[2 * np + 1], ah, bl[2], bl[3]);
            }
        }
    }

    // --- epilogue: write 128x64 fp32 tile ---
    const int mrow = row0 + wid * 16 + (lane >> 2);
    const int ncol = (lane & 3) * 2;
    #pragma unroll
    for (int nt = 0; nt < 8; nt++) {
        float2 v0 = make_float2(c[nt][0], c[nt][1]);
        float2 v1 = make_float2(c[nt][2], c[nt][3]);
        *(float2*)(g_conv + (size_t)mrow * COUT + nt * 8 + ncol)       = v0;
        *(float2*)(g_conv + (size_t)(mrow + 8) * COUT + nt * 8 + ncol) = v1;
    }
}

// ----------------------------------------------------------------------------
// Kernel 4: per-channel sum / sumsq.  512 blocks x 256 threads.
// ----------------------------------------------------------------------------
__global__ void stats_kernel() {
    __shared__ float s1[256], s2[256];
    int tid = threadIdx.x;
    int c   = tid & 63;
    int sub = tid >> 6;
    float a1 = 0.f, a2 = 0.f;
    int rbeg = blockIdx.x * 512 + sub;
    int rend = blockIdx.x * 512 + 512;
    for (int r = rbeg; r < rend; r += 4) {
        float v = g_conv[(size_t)r * COUT + c];
        a1 += v;
        a2 += v * v;
    }
    s1[tid] = a1; s2[tid] = a2;
    __syncthreads();
    if (tid < 64) {
        float t1 = s1[tid] + s1[tid + 64] + s1[tid + 128] + s1[tid + 192];
        float t2 = s2[tid] + s2[tid + 64] + s2[tid + 128] + s2[tid + 192];
        atomicAdd(&g_stats[tid],      t1);
        atomicAdd(&g_stats[64 + tid], t2);
    }
}

// ----------------------------------------------------------------------------
// Kernel 5: finalize BN scale/shift
// ----------------------------------------------------------------------------
__global__ void finalize_kernel(const float* __restrict__ gamma,
                                const float* __restrict__ beta) {
    int c = threadIdx.x;
    if (c < COUT) {
        float mean = g_stats[c] * (1.f / (float)NPTS);
        float var  = g_stats[64 + c] * (1.f / (float)NPTS) - mean * mean;
        float sc   = gamma[c] * rsqrtf(var + EPSV);
        g_stats[128 + c] = sc;
        g_stats[192 + c] = beta[c] - mean * sc;
    }
}

// ----------------------------------------------------------------------------
// Kernel 6: apply BN + ReLU
// ----------------------------------------------------------------------------
__global__ void apply_kernel(float* __restrict__ out) {
    int i = blockIdx.x * blockDim.x + threadIdx.x;      // float4 index, exact grid
    float4 v = *((const float4*)g_conv + i);
    int cq = (i & 15) * 4;
    float4 sc = *(const float4*)(&g_stats[128 + cq]);
    float4 sh = *(const float4*)(&g_stats[192 + cq]);
    v.x = fmaxf(fmaf(v.x, sc.x, sh.x), 0.f);
    v.y = fmaxf(fmaf(v.y, sc.y, sh.y), 0.f);
    v.z = fmaxf(fmaf(v.z, sc.z, sh.z), 0.f);
    v.w = fmaxf(fmaf(v.w, sc.w, sh.w), 0.f);
    ((float4*)out)[i] = v;
}

// ----------------------------------------------------------------------------
// Launch
// ----------------------------------------------------------------------------
extern "C" void kernel_launch(void* const* d_in, const int* in_sizes, int n_in,
                              void* d_out, int out_size) {
    const float* feat  = (const float*)d_in[0];
    const int*   nbr   = (const int*)d_in[1];
    const float* w     = (const float*)d_in[2];
    const float* gamma = (const float*)d_in[3];
    const float* beta  = (const float*)d_in[4];
    float*       out   = (float*)d_out;
    (void)in_sizes; (void)n_in; (void)out_size;

    cudaFuncSetAttribute(conv_kernel,
                         cudaFuncAttributeMaxDynamicSharedMemorySize, CONV_SMEM);

    {
        int total4 = (NPTS + 1) * 16;
        prep_feat_kernel<<<(total4 + 255) / 256, 256>>>(feat);
    }
    prep_w_kernel<<<KOFF + 1, 256>>>(w);
    conv_kernel<<<NTILES, 256, CONV_SMEM>>>(nbr);
    stats_kernel<<<512, 256>>>();
    finalize_kernel<<<1, 64>>>(gamma, beta);
    apply_kernel<<<(NPTS * COUT / 4) / 256, 256>>>(out);
}

// round 4
// speedup vs baseline: 1.9831x; 1.9831x over previous
#include <cuda_runtime.h>
#include <cuda_fp16.h>
#include <cstdint>

// ----------------------------------------------------------------------------
// Problem constants
// ----------------------------------------------------------------------------
#define NPTS   262144
#define KOFF   27
#define CIN    64
#define COUT   64
#define TILE_M 256
#define NTILES (NPTS / TILE_M)   // 1024
#define EPSV   1e-5f

// ----------------------------------------------------------------------------
// Device scratch (static allocations only)
// ----------------------------------------------------------------------------
// Features as fp16 (hi only), 128B per row; extra zero row at index NPTS.
__device__ __half g_feat[(size_t)(NPTS + 1) * 64];
// Weights, transposed + split: [k][{hi,lo}][co][ci] fp16
__device__ __half g_wt[(size_t)KOFF * 2 * COUT * CIN];
__device__ float  g_conv[(size_t)NPTS * COUT];   // conv output before BN
__device__ float  g_stats[256];                  // [0:64) sum [64:128) sumsq
                                                 // [128:192) scale [192:256) shift

// ----------------------------------------------------------------------------
// Helpers
// ----------------------------------------------------------------------------
__device__ __forceinline__ uint32_t smem_u32(const void* p) {
    uint32_t a;
    asm("{ .reg .u64 t; cvta.to.shared.u64 t, %1; cvt.u32.u64 %0, t; }"
        : "=r"(a) : "l"(p));
    return a;
}

__device__ __forceinline__ void ldsm4(uint32_t* r, uint32_t addr) {
    asm volatile("ldmatrix.sync.aligned.m8n8.x4.shared.b16 {%0,%1,%2,%3}, [%4];"
                 : "=r"(r[0]), "=r"(r[1]), "=r"(r[2]), "=r"(r[3]) : "r"(addr));
}

__device__ __forceinline__ void mma16816(float* c, const uint32_t* a,
                                         uint32_t b0, uint32_t b1) {
    asm volatile(
        "mma.sync.aligned.m16n8k16.row.col.f32.f16.f16.f32 "
        "{%0,%1,%2,%3}, {%4,%5,%6,%7}, {%8,%9}, {%0,%1,%2,%3};"
        : "+f"(c[0]), "+f"(c[1]), "+f"(c[2]), "+f"(c[3])
        : "r"(a[0]), "r"(a[1]), "r"(a[2]), "r"(a[3]), "r"(b0), "r"(b1));
}

__device__ __forceinline__ void cp16(uint32_t smem_dst, const void* gsrc) {
    asm volatile("cp.async.cg.shared.global [%0], [%1], 16;"
                 :: "r"(smem_dst), "l"(gsrc));
}

// ----------------------------------------------------------------------------
// Kernel 1: features f32 -> fp16, 128B rows; zero pad row at index NPTS
// ----------------------------------------------------------------------------
__global__ void prep_feat_kernel(const float* __restrict__ feat) {
    const int total4 = (NPTS + 1) * 16;          // float4 count
    int i = blockIdx.x * blockDim.x + threadIdx.x;
    if (i >= total4) return;
    float4 v;
    if (i < NPTS * 16) v = ((const float4*)feat)[i];
    else               v = make_float4(0.f, 0.f, 0.f, 0.f);

    int row = i >> 4, c4 = i & 15;
    __half2* hi = (__half2*)(g_feat + (size_t)row * 64 + c4 * 4);
    hi[0] = __halves2half2(__float2half_rn(v.x), __float2half_rn(v.y));
    hi[1] = __halves2half2(__float2half_rn(v.z), __float2half_rn(v.w));
}

// ----------------------------------------------------------------------------
// Kernel 2: weights [k][ci][co] -> [k][{hi,lo}][co][ci]; zero stats accums
// ----------------------------------------------------------------------------
__global__ void prep_w_kernel(const float* __restrict__ w) {
    int k = blockIdx.x;
    if (k == KOFF) {
        if (threadIdx.x < 128) g_stats[threadIdx.x] = 0.f;
        return;
    }
    for (int idx = threadIdx.x; idx < CIN * COUT; idx += blockDim.x) {
        int ci = idx / COUT, co = idx % COUT;
        float f = w[(size_t)k * CIN * COUT + idx];
        __half hi = __float2half_rn(f);
        __half lo = __float2half_rn(f - __half2float(hi));
        size_t base = (size_t)k * 2 * COUT * CIN;
        g_wt[base + (size_t)co * CIN + ci]              = hi;
        g_wt[base + COUT * CIN + (size_t)co * CIN + ci] = lo;
    }
}

// ----------------------------------------------------------------------------
// Kernel 3: cp.async-pipelined gather + mma.sync conv.
// 1024 CTAs x 256 threads (8 warps, warp grid 4M x 2N, 64x32 per warp).
// Stage (48KB): A[256][128B] | W_hi[64][128B] | W_lo[64][128B], XOR-quad
// swizzle (quad q at physical (q ^ (row&7))). Two stages, cp.async pipeline.
// ----------------------------------------------------------------------------
#define STAGE   49152
#define W_OFF   32768
#define CONV_SMEM (2 * STAGE)

__global__ void __launch_bounds__(256, 2) conv_kernel(const int* __restrict__ nbr) {
    extern __shared__ char smem[];
    const uint32_t sb  = smem_u32(smem);
    const int tid  = threadIdx.x;
    const int wid  = tid >> 5;
    const int lane = tid & 31;
    const int wm   = wid >> 1;          // 0..3 -> m base wm*64
    const int wn   = wid & 1;           // n base wn*32
    const int row0 = blockIdx.x * TILE_M;

    float c[4][2][2][4];                // [mt][nc][n8][frag]
    #pragma unroll
    for (int a = 0; a < 4; a++)
        #pragma unroll
        for (int b = 0; b < 2; b++)
            #pragma unroll
            for (int d = 0; d < 2; d++)
                #pragma unroll
                for (int j = 0; j < 4; j++) c[a][b][d][j] = 0.f;

    const int*     idxp = nbr + row0 + tid;     // this thread's gather row
    const uint32_t srow7 = (uint32_t)(tid & 7); // swizzle key for its row

    // --- preload k=0 into stage 0 ---
    int g_next = __ldg(idxp);                   // idx for k=0
    {
        const int4* fr = (const int4*)g_feat + (size_t)g_next * 8;
        #pragma unroll
        for (int q = 0; q < 8; q++)
            cp16(sb + (uint32_t)tid * 128 + (((uint32_t)q ^ srow7) << 4), fr + q);
        const int4* wsrc = (const int4*)g_wt;
        #pragma unroll
        for (int j = 0; j < 4; j++) {
            int lin = tid + j * 256;
            int rr = lin >> 3, q = lin & 7;
            cp16(sb + W_OFF + rr * 128 + (((uint32_t)q ^ (uint32_t)(rr & 7)) << 4),
                 wsrc + lin);
        }
        asm volatile("cp.async.commit_group;");
    }
    g_next = __ldg(idxp + NPTS);                // idx for k=1

    // ldmatrix invariants
    const uint32_t arow  = (uint32_t)(wm * 64 + (lane & 15));
    const uint32_t aswz  = (uint32_t)((lane & 15) & 7);
    const uint32_t ahalf = (uint32_t)(lane >> 4);
    const uint32_t brow  = (uint32_t)(wn * 32 + (lane & 7) + ((lane >> 4) << 3));
    const uint32_t bswz  = (uint32_t)(lane & 7);
    const uint32_t bhalf = (uint32_t)((lane >> 3) & 1);

    for (int k = 0; k < KOFF; k++) {
        const int buf = k & 1;

        if (k + 1 < KOFF) {
            // issue gather for k+1 into other stage (overlaps this k's MMA wait)
            const uint32_t nb = sb + (uint32_t)(buf ^ 1) * STAGE;
            const int4* fr = (const int4*)g_feat + (size_t)g_next * 8;
            #pragma unroll
            for (int q = 0; q < 8; q++)
                cp16(nb + (uint32_t)tid * 128 + (((uint32_t)q ^ srow7) << 4), fr + q);
            const int4* wsrc = (const int4*)(g_wt + (size_t)(k + 1) * 2 * COUT * CIN);
            #pragma unroll
            for (int j = 0; j < 4; j++) {
                int lin = tid + j * 256;
                int rr = lin >> 3, q = lin & 7;
                cp16(nb + W_OFF + rr * 128 + (((uint32_t)q ^ (uint32_t)(rr & 7)) << 4),
                     wsrc + lin);
            }
            asm volatile("cp.async.commit_group;");
            if (k + 2 < KOFF) g_next = __ldg(idxp + (size_t)(k + 2) * NPTS);
            asm volatile("cp.async.wait_group 1;");
        } else {
            asm volatile("cp.async.wait_group 0;");
        }
        __syncthreads();   // stage buf fully resident for all threads

        const uint32_t A0 = sb + (uint32_t)buf * STAGE;
        const uint32_t WH = A0 + W_OFF;
        const uint32_t WL = A0 + W_OFF + 8192;

        #pragma unroll
        for (int ks = 0; ks < 4; ks++) {
            const uint32_t aoff = (((uint32_t)(2 * ks) + ahalf) ^ aswz) << 4;
            uint32_t ah[4][4];
            #pragma unroll
            for (int mt = 0; mt < 4; mt++)
                ldsm4(ah[mt], A0 + (arow + mt * 16) * 128 + aoff);
            const uint32_t boff = (((uint32_t)(2 * ks) + bhalf) ^ bswz) << 4;
            #pragma unroll
            for (int nc = 0; nc < 2; nc++) {
                uint32_t bh[4], bl[4];
                ldsm4(bh, WH + (brow + nc * 16) * 128 + boff);
                ldsm4(bl, WL + (brow + nc * 16) * 128 + boff);
                #pragma unroll
                for (int mt = 0; mt < 4; mt++) {
                    mma16816(c[mt][nc][0], ah[mt], bh[0], bh[1]);
                    mma16816(c[mt][nc][1], ah[mt], bh[2], bh[3]);
                    mma16816(c[mt][nc][0], ah[mt], bl[0], bl[1]);
                    mma16816(c[mt][nc][1], ah[mt], bl[2], bl[3]);
                }
            }
        }
        __syncthreads();   // MMA done before next iteration overwrites buf^1
    }

    // --- epilogue: write 256x64 fp32 tile + per-channel partial stats ---
    const int r0 = row0 + wm * 64 + (lane >> 2);
    const int cb = wn * 32 + (lane & 3) * 2;
    float ls[2][2][2], lq[2][2][2];     // [nc][n8][j] sums / sumsqs
    #pragma unroll
    for (int nc = 0; nc < 2; nc++)
        #pragma unroll
        for (int n8 = 0; n8 < 2; n8++)
            #pragma unroll
            for (int j = 0; j < 2; j++) { ls[nc][n8][j] = 0.f; lq[nc][n8][j] = 0.f; }

    #pragma unroll
    for (int mt = 0; mt < 4; mt++) {
        const int r = r0 + mt * 16;
        #pragma unroll
        for (int nc = 0; nc < 2; nc++) {
            #pragma unroll
            for (int n8 = 0; n8 < 2; n8++) {
                const int col = cb + nc * 16 + n8 * 8;
                float v0 = c[mt][nc][n8][0], v1 = c[mt][nc][n8][1];
                float v2 = c[mt][nc][n8][2], v3 = c[mt][nc][n8][3];
                *(float2*)(g_conv + (size_t)r * COUT + col)       = make_float2(v0, v1);
                *(float2*)(g_conv + (size_t)(r + 8) * COUT + col) = make_float2(v2, v3);
                ls[nc][n8][0] += v0 + v2;  lq[nc][n8][0] += v0 * v0 + v2 * v2;
                ls[nc][n8][1] += v1 + v3;  lq[nc][n8][1] += v1 * v1 + v3 * v3;
            }
        }
    }

    // reduce across the 8 lanes sharing (lane & 3)
    #pragma unroll
    for (int nc = 0; nc < 2; nc++)
        #pragma unroll
        for (int n8 = 0; n8 < 2; n8++)
            #pragma unroll
            for (int j = 0; j < 2; j++) {
                float s = ls[nc][n8][j], q = lq[nc][n8][j];
                #pragma unroll
                for (int sh = 4; sh <= 16; sh <<= 1) {
                    s += __shfl_xor_sync(0xFFFFFFFFu, s, sh);
                    q += __shfl_xor_sync(0xFFFFFFFFu, q, sh);
                }
                ls[nc][n8][j] = s; lq[nc][n8][j] = q;
            }

    float* sred = (float*)smem;         // reuse stage 0 (all MMA reads done)
    __syncthreads();
    if (tid < 128) sred[tid] = 0.f;
    __syncthreads();
    if ((lane >> 2) == 0) {             // lanes 0..3 per warp
        #pragma unroll
        for (int nc = 0; nc < 2; nc++)
            #pragma unroll
            for (int n8 = 0; n8 < 2; n8++)
                #pragma unroll
                for (int j = 0; j < 2; j++) {
                    const int col = cb + nc * 16 + n8 * 8 + j;
                    atomicAdd(&sred[col],      ls[nc][n8][j]);
                    atomicAdd(&sred[64 + col], lq[nc][n8][j]);
                }
    }
    __syncthreads();
    if (tid < 128) atomicAdd(&g_stats[tid], sred[tid]);
}

// ----------------------------------------------------------------------------
// Kernel 4: finalize BN scale/shift
// ----------------------------------------------------------------------------
__global__ void finalize_kernel(const float* __restrict__ gamma,
                                const float* __restrict__ beta) {
    int c = threadIdx.x;
    if (c < COUT) {
        float mean = g_stats[c] * (1.f / (float)NPTS);
        float var  = g_stats[64 + c] * (1.f / (float)NPTS) - mean * mean;
        float sc   = gamma[c] * rsqrtf(var + EPSV);
        g_stats[128 + c] = sc;
        g_stats[192 + c] = beta[c] - mean * sc;
    }
}

// ----------------------------------------------------------------------------
// Kernel 5: apply BN + ReLU
// ----------------------------------------------------------------------------
__global__ void apply_kernel(float* __restrict__ out) {
    int i = blockIdx.x * blockDim.x + threadIdx.x;      // float4 index, exact grid
    float4 v = *((const float4*)g_conv + i);
    int cq = (i & 15) * 4;
    float4 sc = *(const float4*)(&g_stats[128 + cq]);
    float4 sh = *(const float4*)(&g_stats[192 + cq]);
    v.x = fmaxf(fmaf(v.x, sc.x, sh.x), 0.f);
    v.y = fmaxf(fmaf(v.y, sc.y, sh.y), 0.f);
    v.z = fmaxf(fmaf(v.z, sc.z, sh.z), 0.f);
    v.w = fmaxf(fmaf(v.w, sc.w, sh.w), 0.f);
    ((float4*)out)[i] = v;
}

// ----------------------------------------------------------------------------
// Launch
// ----------------------------------------------------------------------------
extern "C" void kernel_launch(void* const* d_in, const int* in_sizes, int n_in,
                              void* d_out, int out_size) {
    const float* feat  = (const float*)d_in[0];
    const int*   nbr   = (const int*)d_in[1];
    const float* w     = (const float*)d_in[2];
    const float* gamma = (const float*)d_in[3];
    const float* beta  = (const float*)d_in[4];
    float*       out   = (float*)d_out;
    (void)in_sizes; (void)n_in; (void)out_size;

    cudaFuncSetAttribute(conv_kernel,
                         cudaFuncAttributeMaxDynamicSharedMemorySize, CONV_SMEM);

    {
        int total4 = (NPTS + 1) * 16;
        prep_feat_kernel<<<(total4 + 255) / 256, 256>>>(feat);
    }
    prep_w_kernel<<<KOFF + 1, 256>>>(w);
    conv_kernel<<<NTILES, 256, CONV_SMEM>>>(nbr);
    finalize_kernel<<<1, 64>>>(gamma, beta);
    apply_kernel<<<(NPTS * COUT / 4) / 256, 256>>>(out);
}

// round 6
// speedup vs baseline: 2.6024x; 1.3123x over previous
#include <cuda_runtime.h>
#include <cuda_fp16.h>
#include <cstdint>

// ----------------------------------------------------------------------------
// Problem constants
// ----------------------------------------------------------------------------
#define NPTS   262144
#define KOFF   27
#define CIN    64
#define COUT   64
#define TILE_M 256
#define NTILES (NPTS / TILE_M)   // 1024
#define EPSV   1e-5f

// ----------------------------------------------------------------------------
// Device scratch (static allocations only)
// ----------------------------------------------------------------------------
// Features as fp16, 128B per row; extra zero row at index NPTS.
__device__ __half g_feat[(size_t)(NPTS + 1) * 64];
// Weights, transposed: [k][co][ci] fp16
__device__ __half g_wt[(size_t)KOFF * COUT * CIN];
__device__ float  g_conv[(size_t)NPTS * COUT];   // conv output before BN
__device__ float  g_stats[256];                  // [0:64) sum [64:128) sumsq
                                                 // [128:192) scale [192:256) shift

// ----------------------------------------------------------------------------
// Helpers
// ----------------------------------------------------------------------------
__device__ __forceinline__ uint32_t smem_u32(const void* p) {
    uint32_t a;
    asm("{ .reg .u64 t; cvta.to.shared.u64 t, %1; cvt.u32.u64 %0, t; }"
        : "=r"(a) : "l"(p));
    return a;
}

__device__ __forceinline__ void ldsm4(uint32_t* r, uint32_t addr) {
    asm volatile("ldmatrix.sync.aligned.m8n8.x4.shared.b16 {%0,%1,%2,%3}, [%4];"
                 : "=r"(r[0]), "=r"(r[1]), "=r"(r[2]), "=r"(r[3]) : "r"(addr));
}

__device__ __forceinline__ void mma16816(float* c, const uint32_t* a,
                                         uint32_t b0, uint32_t b1) {
    asm volatile(
        "mma.sync.aligned.m16n8k16.row.col.f32.f16.f16.f32 "
        "{%0,%1,%2,%3}, {%4,%5,%6,%7}, {%8,%9}, {%0,%1,%2,%3};"
        : "+f"(c[0]), "+f"(c[1]), "+f"(c[2]), "+f"(c[3])
        : "r"(a[0]), "r"(a[1]), "r"(a[2]), "r"(a[3]), "r"(b0), "r"(b1));
}

__device__ __forceinline__ void cp16(uint32_t smem_dst, const void* gsrc) {
    asm volatile("cp.async.cg.shared.global [%0], [%1], 16;"
                 :: "r"(smem_dst), "l"(gsrc));
}

// ----------------------------------------------------------------------------
// Kernel 1: features f32 -> fp16, 128B rows; zero pad row at index NPTS
// ----------------------------------------------------------------------------
__global__ void prep_feat_kernel(const float* __restrict__ feat) {
    const int total4 = (NPTS + 1) * 16;          // float4 count
    int i = blockIdx.x * blockDim.x + threadIdx.x;
    if (i >= total4) return;
    float4 v;
    if (i < NPTS * 16) v = ((const float4*)feat)[i];
    else               v = make_float4(0.f, 0.f, 0.f, 0.f);

    int row = i >> 4, c4 = i & 15;
    __half2* hi = (__half2*)(g_feat + (size_t)row * 64 + c4 * 4);
    hi[0] = __halves2half2(__float2half_rn(v.x), __float2half_rn(v.y));
    hi[1] = __halves2half2(__float2half_rn(v.z), __float2half_rn(v.w));
}

// ----------------------------------------------------------------------------
// Kernel 2: weights [k][ci][co] -> [k][co][ci] fp16; zero stats accums
// ----------------------------------------------------------------------------
__global__ void prep_w_kernel(const float* __restrict__ w) {
    int k = blockIdx.x;
    if (k == KOFF) {
        if (threadIdx.x < 128) g_stats[threadIdx.x] = 0.f;
        return;
    }
    for (int idx = threadIdx.x; idx < CIN * COUT; idx += blockDim.x) {
        int ci = idx / COUT, co = idx % COUT;
        float f = w[(size_t)k * CIN * COUT + idx];
        g_wt[(size_t)k * COUT * CIN + (size_t)co * CIN + ci] = __float2half_rn(f);
    }
}

// ----------------------------------------------------------------------------
// Kernel 3: cp.async-pipelined gather + mma.sync conv.
// 1024 CTAs x 256 threads (8 warps, warp grid 4M x 2N, 64x32 per warp).
// Stage (40KB): A[256][128B] | W[64][128B], XOR-quad swizzle
// (quad q at physical (q ^ (row&7))). Two stages, cp.async pipeline.
// ----------------------------------------------------------------------------
#define STAGE   40960
#define W_OFF   32768
#define CONV_SMEM (2 * STAGE)

__global__ void __launch_bounds__(256, 2) conv_kernel(const int* __restrict__ nbr) {
    extern __shared__ char smem[];
    const uint32_t sb  = smem_u32(smem);
    const int tid  = threadIdx.x;
    const int wid  = tid >> 5;
    const int lane = tid & 31;
    const int wm   = wid >> 1;          // 0..3 -> m base wm*64
    const int wn   = wid & 1;           // n base wn*32
    const int row0 = blockIdx.x * TILE_M;

    float c[4][2][2][4];                // [mt][nc][n8][frag]
    #pragma unroll
    for (int a = 0; a < 4; a++)
        #pragma unroll
        for (int b = 0; b < 2; b++)
            #pragma unroll
            for (int d = 0; d < 2; d++)
                #pragma unroll
                for (int j = 0; j < 4; j++) c[a][b][d][j] = 0.f;

    const int*     idxp = nbr + row0 + tid;     // this thread's gather row
    const uint32_t srow7 = (uint32_t)(tid & 7); // swizzle key for its row

    // --- preload k=0 into stage 0 ---
    int g_next = __ldg(idxp);                   // idx for k=0
    {
        const int4* fr = (const int4*)g_feat + (size_t)g_next * 8;
        #pragma unroll
        for (int q = 0; q < 8; q++)
            cp16(sb + (uint32_t)tid * 128 + (((uint32_t)q ^ srow7) << 4), fr + q);
        const int4* wsrc = (const int4*)g_wt;
        #pragma unroll
        for (int j = 0; j < 2; j++) {
            int lin = tid + j * 256;            // 0..511
            int rr = lin >> 3, q = lin & 7;
            cp16(sb + W_OFF + rr * 128 + (((uint32_t)q ^ (uint32_t)(rr & 7)) << 4),
                 wsrc + lin);
        }
        asm volatile("cp.async.commit_group;");
    }
    g_next = __ldg(idxp + NPTS);                // idx for k=1

    // ldmatrix invariants
    const uint32_t arow  = (uint32_t)(wm * 64 + (lane & 15));
    const uint32_t aswz  = (uint32_t)((lane & 15) & 7);
    const uint32_t ahalf = (uint32_t)(lane >> 4);
    const uint32_t brow  = (uint32_t)(wn * 32 + (lane & 7) + ((lane >> 4) << 3));
    const uint32_t bswz  = (uint32_t)(lane & 7);
    const uint32_t bhalf = (uint32_t)((lane >> 3) & 1);

    for (int k = 0; k < KOFF; k++) {
        const int buf = k & 1;

        if (k + 1 < KOFF) {
            // issue gather for k+1 into other stage (overlaps this k's MMA wait)
            const uint32_t nb = sb + (uint32_t)(buf ^ 1) * STAGE;
            const int4* fr = (const int4*)g_feat + (size_t)g_next * 8;
            #pragma unroll
            for (int q = 0; q < 8; q++)
                cp16(nb + (uint32_t)tid * 128 + (((uint32_t)q ^ srow7) << 4), fr + q);
            const int4* wsrc = (const int4*)(g_wt + (size_t)(k + 1) * COUT * CIN);
            #pragma unroll
            for (int j = 0; j < 2; j++) {
                int lin = tid + j * 256;
                int rr = lin >> 3, q = lin & 7;
                cp16(nb + W_OFF + rr * 128 + (((uint32_t)q ^ (uint32_t)(rr & 7)) << 4),
                     wsrc + lin);
            }
            asm volatile("cp.async.commit_group;");
            if (k + 2 < KOFF) g_next = __ldg(idxp + (size_t)(k + 2) * NPTS);
            asm volatile("cp.async.wait_group 1;");
        } else {
            asm volatile("cp.async.wait_group 0;");
        }
        __syncthreads();   // stage buf fully resident for all threads

        const uint32_t A0 = sb + (uint32_t)buf * STAGE;
        const uint32_t WH = A0 + W_OFF;

        #pragma unroll
        for (int ks = 0; ks < 4; ks++) {
            const uint32_t aoff = (((uint32_t)(2 * ks) + ahalf) ^ aswz) << 4;
            uint32_t ah[4][4];
            #pragma unroll
            for (int mt = 0; mt < 4; mt++)
                ldsm4(ah[mt], A0 + (arow + mt * 16) * 128 + aoff);
            const uint32_t boff = (((uint32_t)(2 * ks) + bhalf) ^ bswz) << 4;
            #pragma unroll
            for (int nc = 0; nc < 2; nc++) {
                uint32_t bh[4];
                ldsm4(bh, WH + (brow + nc * 16) * 128 + boff);
                #pragma unroll
                for (int mt = 0; mt < 4; mt++) {
                    mma16816(c[mt][nc][0], ah[mt], bh[0], bh[1]);
                    mma16816(c[mt][nc][1], ah[mt], bh[2], bh[3]);
                }
            }
        }
        __syncthreads();   // MMA done before next iteration overwrites buf^1
    }

    // --- epilogue: write 256x64 fp32 tile + per-channel partial stats ---
    const int r0 = row0 + wm * 64 + (lane >> 2);
    const int cb = wn * 32 + (lane & 3) * 2;
    float ls[2][2][2], lq[2][2][2];     // [nc][n8][j] sums / sumsqs
    #pragma unroll
    for (int nc = 0; nc < 2; nc++)
        #pragma unroll
        for (int n8 = 0; n8 < 2; n8++)
            #pragma unroll
            for (int j = 0; j < 2; j++) { ls[nc][n8][j] = 0.f; lq[nc][n8][j] = 0.f; }

    #pragma unroll
    for (int mt = 0; mt < 4; mt++) {
        const int r = r0 + mt * 16;
        #pragma unroll
        for (int nc = 0; nc < 2; nc++) {
            #pragma unroll
            for (int n8 = 0; n8 < 2; n8++) {
                const int col = cb + nc * 16 + n8 * 8;
                float v0 = c[mt][nc][n8][0], v1 = c[mt][nc][n8][1];
                float v2 = c[mt][nc][n8][2], v3 = c[mt][nc][n8][3];
                *(float2*)(g_conv + (size_t)r * COUT + col)       = make_float2(v0, v1);
                *(float2*)(g_conv + (size_t)(r + 8) * COUT + col) = make_float2(v2, v3);
                ls[nc][n8][0] += v0 + v2;  lq[nc][n8][0] += v0 * v0 + v2 * v2;
                ls[nc][n8][1] += v1 + v3;  lq[nc][n8][1] += v1 * v1 + v3 * v3;
            }
        }
    }

    // reduce across the 8 lanes sharing (lane & 3)
    #pragma unroll
    for (int nc = 0; nc < 2; nc++)
        #pragma unroll
        for (int n8 = 0; n8 < 2; n8++)
            #pragma unroll
            for (int j = 0; j < 2; j++) {
                float s = ls[nc][n8][j], q = lq[nc][n8][j];
                #pragma unroll
                for (int sh = 4; sh <= 16; sh <<= 1) {
                    s += __shfl_xor_sync(0xFFFFFFFFu, s, sh);
                    q += __shfl_xor_sync(0xFFFFFFFFu, q, sh);
                }
                ls[nc][n8][j] = s; lq[nc][n8][j] = q;
            }

    float* sred = (float*)smem;         // reuse stage 0 (all MMA reads done)
    __syncthreads();
    if (tid < 128) sred[tid] = 0.f;
    __syncthreads();
    if ((lane >> 2) == 0) {             // lanes 0..3 per warp
        #pragma unroll
        for (int nc = 0; nc < 2; nc++)
            #pragma unroll
            for (int n8 = 0; n8 < 2; n8++)
                #pragma unroll
                for (int j = 0; j < 2; j++) {
                    const int col = cb + nc * 16 + n8 * 8 + j;
                    atomicAdd(&sred[col],      ls[nc][n8][j]);
                    atomicAdd(&sred[64 + col], lq[nc][n8][j]);
                }
    }
    __syncthreads();
    if (tid < 128) atomicAdd(&g_stats[tid], sred[tid]);
}

// ----------------------------------------------------------------------------
// Kernel 4: finalize BN scale/shift
// ----------------------------------------------------------------------------
__global__ void finalize_kernel(const float* __restrict__ gamma,
                                const float* __restrict__ beta) {
    int c = threadIdx.x;
    if (c < COUT) {
        float mean = g_stats[c] * (1.f / (float)NPTS);
        float var  = g_stats[64 + c] * (1.f / (float)NPTS) - mean * mean;
        float sc   = gamma[c] * rsqrtf(var + EPSV);
        g_stats[128 + c] = sc;
        g_stats[192 + c] = beta[c] - mean * sc;
    }
}

// ----------------------------------------------------------------------------
// Kernel 5: apply BN + ReLU
// ----------------------------------------------------------------------------
__global__ void apply_kernel(float* __restrict__ out) {
    int i = blockIdx.x * blockDim.x + threadIdx.x;      // float4 index, exact grid
    float4 v = *((const float4*)g_conv + i);
    int cq = (i & 15) * 4;
    float4 sc = *(const float4*)(&g_stats[128 + cq]);
    float4 sh = *(const float4*)(&g_stats[192 + cq]);
    v.x = fmaxf(fmaf(v.x, sc.x, sh.x), 0.f);
    v.y = fmaxf(fmaf(v.y, sc.y, sh.y), 0.f);
    v.z = fmaxf(fmaf(v.z, sc.z, sh.z), 0.f);
    v.w = fmaxf(fmaf(v.w, sc.w, sh.w), 0.f);
    ((float4*)out)[i] = v;
}

// ----------------------------------------------------------------------------
// Launch
// ----------------------------------------------------------------------------
extern "C" void kernel_launch(void* const* d_in, const int* in_sizes, int n_in,
                              void* d_out, int out_size) {
    const float* feat  = (const float*)d_in[0];
    const int*   nbr   = (const int*)d_in[1];
    const float* w     = (const float*)d_in[2];
    const float* gamma = (const float*)d_in[3];
    const float* beta  = (const float*)d_in[4];
    float*       out   = (float*)d_out;
    (void)in_sizes; (void)n_in; (void)out_size;

    cudaFuncSetAttribute(conv_kernel,
                         cudaFuncAttributeMaxDynamicSharedMemorySize, CONV_SMEM);

    {
        int total4 = (NPTS + 1) * 16;
        prep_feat_kernel<<<(total4 + 255) / 256, 256>>>(feat);
    }
    prep_w_kernel<<<KOFF + 1, 256>>>(w);
    conv_kernel<<<NTILES, 256, CONV_SMEM>>>(nbr);
    finalize_kernel<<<1, 64>>>(gamma, beta);
    apply_kernel<<<(NPTS * COUT / 4) / 256, 256>>>(out);
}

// round 7
// speedup vs baseline: 3.2228x; 1.2384x over previous
#include <cuda_runtime.h>
#include <cuda_fp16.h>
#include <cstdint>

// ----------------------------------------------------------------------------
// Problem constants
// ----------------------------------------------------------------------------
#define NPTS   262144
#define KOFF   27
#define CIN    64
#define COUT   64
#define TILE_M 128
#define NTILES (NPTS / TILE_M)   // 2048
#define EPSV   1e-5f

// ----------------------------------------------------------------------------
// Device scratch (static allocations only)
// ----------------------------------------------------------------------------
// Features as fp16, 128B per row; extra zero row at index NPTS.
__device__ __half g_feat[(size_t)(NPTS + 1) * 64];
// Weights, transposed: [k][co][ci] fp16
__device__ __half g_wt[(size_t)KOFF * COUT * CIN];
__device__ float  g_conv[(size_t)NPTS * COUT];   // conv output before BN
__device__ float  g_stats[256];                  // [0:64) sum [64:128) sumsq
                                                 // [128:192) scale [192:256) shift

// ----------------------------------------------------------------------------
// Helpers
// ----------------------------------------------------------------------------
__device__ __forceinline__ uint32_t smem_u32(const void* p) {
    uint32_t a;
    asm("{ .reg .u64 t; cvta.to.shared.u64 t, %1; cvt.u32.u64 %0, t; }"
        : "=r"(a) : "l"(p));
    return a;
}

__device__ __forceinline__ void ldsm4(uint32_t* r, uint32_t addr) {
    asm volatile("ldmatrix.sync.aligned.m8n8.x4.shared.b16 {%0,%1,%2,%3}, [%4];"
                 : "=r"(r[0]), "=r"(r[1]), "=r"(r[2]), "=r"(r[3]) : "r"(addr));
}

__device__ __forceinline__ void mma16816(float* c, const uint32_t* a,
                                         uint32_t b0, uint32_t b1) {
    asm volatile(
        "mma.sync.aligned.m16n8k16.row.col.f32.f16.f16.f32 "
        "{%0,%1,%2,%3}, {%4,%5,%6,%7}, {%8,%9}, {%0,%1,%2,%3};"
        : "+f"(c[0]), "+f"(c[1]), "+f"(c[2]), "+f"(c[3])
        : "r"(a[0]), "r"(a[1]), "r"(a[2]), "r"(a[3]), "r"(b0), "r"(b1));
}

__device__ __forceinline__ void cp16(uint32_t smem_dst, const void* gsrc) {
    asm volatile("cp.async.cg.shared.global [%0], [%1], 16;"
                 :: "r"(smem_dst), "l"(gsrc));
}

// ----------------------------------------------------------------------------
// Kernel 1: features f32 -> fp16, 128B rows; zero pad row at index NPTS
// ----------------------------------------------------------------------------
__global__ void prep_feat_kernel(const float* __restrict__ feat) {
    const int total4 = (NPTS + 1) * 16;          // float4 count
    int i = blockIdx.x * blockDim.x + threadIdx.x;
    if (i >= total4) return;
    float4 v;
    if (i < NPTS * 16) v = ((const float4*)feat)[i];
    else               v = make_float4(0.f, 0.f, 0.f, 0.f);

    int row = i >> 4, c4 = i & 15;
    __half2* hi = (__half2*)(g_feat + (size_t)row * 64 + c4 * 4);
    hi[0] = __halves2half2(__float2half_rn(v.x), __float2half_rn(v.y));
    hi[1] = __halves2half2(__float2half_rn(v.z), __float2half_rn(v.w));
}

// ----------------------------------------------------------------------------
// Kernel 2: weights [k][ci][co] -> [k][co][ci] fp16; zero stats accums
// ----------------------------------------------------------------------------
__global__ void prep_w_kernel(const float* __restrict__ w) {
    int k = blockIdx.x;
    if (k == KOFF) {
        if (threadIdx.x < 128) g_stats[threadIdx.x] = 0.f;
        return;
    }
    for (int idx = threadIdx.x; idx < CIN * COUT; idx += blockDim.x) {
        int ci = idx / COUT, co = idx % COUT;
        float f = w[(size_t)k * CIN * COUT + idx];
        g_wt[(size_t)k * COUT * CIN + (size_t)co * CIN + ci] = __float2half_rn(f);
    }
}

// ----------------------------------------------------------------------------
// Kernel 3: 4-stage cp.async-pipelined gather + mma.sync conv.
// 2048 CTAs x 256 threads (8 warps, warp grid 4M x 2N, 32x32 per warp).
// Stage (24KB): A[128][128B] | W[64][128B], XOR-quad swizzle.
// One __syncthreads per k; fill(k+3) issued after barrier, covered by 3 MMA
// phases.  Hazard-free: fill(k+3) targets the buffer last read by MMA(k-1),
// retired by this iteration's barrier.
// ----------------------------------------------------------------------------
#define STAGE    24576
#define W_OFF    16384
#define NSTAGE   4
#define CONV_SMEM (NSTAGE * STAGE)

__device__ __forceinline__ void fill_stage(uint32_t buf, int g, int k,
                                           int tid) {
    // A: thread covers row tid>>1, half tid&1 (4 x int4 = 64B)
    const int row  = tid >> 1;
    const int half = tid & 1;
    const uint32_t key = (uint32_t)(row & 7);
    const int4* fr = (const int4*)g_feat + (size_t)g * 8 + half * 4;
    #pragma unroll
    for (int q = 0; q < 4; q++) {
        uint32_t qq = (uint32_t)(half * 4 + q);
        cp16(buf + (uint32_t)row * 128 + ((qq ^ key) << 4), fr + q);
    }
    // W: 512 int4, 2 per thread
    const int4* wsrc = (const int4*)(g_wt + (size_t)k * COUT * CIN);
    #pragma unroll
    for (int j = 0; j < 2; j++) {
        int lin = tid + j * 256;
        int rr = lin >> 3, q = lin & 7;
        cp16(buf + W_OFF + rr * 128 + (((uint32_t)q ^ (uint32_t)(rr & 7)) << 4),
             wsrc + lin);
    }
    asm volatile("cp.async.commit_group;");
}

__global__ void __launch_bounds__(256, 2) conv_kernel(const int* __restrict__ nbr) {
    extern __shared__ char smem[];
    const uint32_t sb  = smem_u32(smem);
    const int tid  = threadIdx.x;
    const int wid  = tid >> 5;
    const int lane = tid & 31;
    const int wm   = wid >> 1;          // 0..3 -> m base wm*32
    const int wn   = wid & 1;           // n base wn*32
    const int row0 = blockIdx.x * TILE_M;

    float c[2][2][2][4];                // [mt][nc][n8][frag]
    #pragma unroll
    for (int a = 0; a < 2; a++)
        #pragma unroll
        for (int b = 0; b < 2; b++)
            #pragma unroll
            for (int d = 0; d < 2; d++)
                #pragma unroll
                for (int j = 0; j < 4; j++) c[a][b][d][j] = 0.f;

    const int* idxp = nbr + row0 + (tid >> 1);  // this thread's gather row

    // --- prologue: fill stages for k = 0,1,2 ---
    {
        int g0 = __ldg(idxp);
        int g1 = __ldg(idxp + NPTS);
        int g2 = __ldg(idxp + 2 * NPTS);
        fill_stage(sb,             g0, 0, tid);
        fill_stage(sb + STAGE,     g1, 1, tid);
        fill_stage(sb + 2 * STAGE, g2, 2, tid);
    }
    int g_next = __ldg(idxp + (size_t)3 * NPTS);   // idx for k=3

    // ldmatrix invariants
    const uint32_t arow  = (uint32_t)(wm * 32 + (lane & 15));
    const uint32_t aswz  = (uint32_t)((lane & 15) & 7);
    const uint32_t ahalf = (uint32_t)(lane >> 4);
    const uint32_t brow  = (uint32_t)(wn * 32 + (lane & 7) + ((lane >> 4) << 3));
    const uint32_t bswz  = (uint32_t)(lane & 7);
    const uint32_t bhalf = (uint32_t)((lane >> 3) & 1);

    for (int k = 0; k < KOFF; k++) {
        // wait until fill(k) is complete (per-thread), then barrier for
        // cross-thread visibility AND to retire MMA(k-1) before refilling
        // its buffer.
        if (k < KOFF - 2)       asm volatile("cp.async.wait_group 2;");
        else if (k == KOFF - 2) asm volatile("cp.async.wait_group 1;");
        else                    asm volatile("cp.async.wait_group 0;");
        __syncthreads();

        if (k + 3 < KOFF) {
            fill_stage(sb + (uint32_t)((k + 3) & 3) * STAGE, g_next, k + 3, tid);
            if (k + 4 < KOFF) g_next = __ldg(idxp + (size_t)(k + 4) * NPTS);
        }

        const uint32_t A0 = sb + (uint32_t)(k & 3) * STAGE;
        const uint32_t WH = A0 + W_OFF;

        #pragma unroll
        for (int ks = 0; ks < 4; ks++) {
            const uint32_t aoff = (((uint32_t)(2 * ks) + ahalf) ^ aswz) << 4;
            uint32_t ah[2][4];
            #pragma unroll
            for (int mt = 0; mt < 2; mt++)
                ldsm4(ah[mt], A0 + (arow + mt * 16) * 128 + aoff);
            const uint32_t boff = (((uint32_t)(2 * ks) + bhalf) ^ bswz) << 4;
            #pragma unroll
            for (int nc = 0; nc < 2; nc++) {
                uint32_t bh[4];
                ldsm4(bh, WH + (brow + nc * 16) * 128 + boff);
                #pragma unroll
                for (int mt = 0; mt < 2; mt++) {
                    mma16816(c[mt][nc][0], ah[mt], bh[0], bh[1]);
                    mma16816(c[mt][nc][1], ah[mt], bh[2], bh[3]);
                }
            }
        }
        // no trailing barrier: next iteration's barrier retires these MMAs
    }

    // --- epilogue: write 128x64 fp32 tile + per-channel partial stats ---
    const int r0 = row0 + wm * 32 + (lane >> 2);
    const int cb = wn * 32 + (lane & 3) * 2;
    float ls[2][2][2], lq[2][2][2];     // [nc][n8][j] sums / sumsqs
    #pragma unroll
    for (int nc = 0; nc < 2; nc++)
        #pragma unroll
        for (int n8 = 0; n8 < 2; n8++)
            #pragma unroll
            for (int j = 0; j < 2; j++) { ls[nc][n8][j] = 0.f; lq[nc][n8][j] = 0.f; }

    #pragma unroll
    for (int mt = 0; mt < 2; mt++) {
        const int r = r0 + mt * 16;
        #pragma unroll
        for (int nc = 0; nc < 2; nc++) {
            #pragma unroll
            for (int n8 = 0; n8 < 2; n8++) {
                const int col = cb + nc * 16 + n8 * 8;
                float v0 = c[mt][nc][n8][0], v1 = c[mt][nc][n8][1];
                float v2 = c[mt][nc][n8][2], v3 = c[mt][nc][n8][3];
                *(float2*)(g_conv + (size_t)r * COUT + col)       = make_float2(v0, v1);
                *(float2*)(g_conv + (size_t)(r + 8) * COUT + col) = make_float2(v2, v3);
                ls[nc][n8][0] += v0 + v2;  lq[nc][n8][0] += v0 * v0 + v2 * v2;
                ls[nc][n8][1] += v1 + v3;  lq[nc][n8][1] += v1 * v1 + v3 * v3;
            }
        }
    }

    // reduce across the 8 lanes sharing (lane & 3)
    #pragma unroll
    for (int nc = 0; nc < 2; nc++)
        #pragma unroll
        for (int n8 = 0; n8 < 2; n8++)
            #pragma unroll
            for (int j = 0; j < 2; j++) {
                float s = ls[nc][n8][j], q = lq[nc][n8][j];
                #pragma unroll
                for (int sh = 4; sh <= 16; sh <<= 1) {
                    s += __shfl_xor_sync(0xFFFFFFFFu, s, sh);
                    q += __shfl_xor_sync(0xFFFFFFFFu, q, sh);
                }
                ls[nc][n8][j] = s; lq[nc][n8][j] = q;
            }

    float* sred = (float*)smem;         // reuse stage 0 (all MMA reads done)
    __syncthreads();
    if (tid < 128) sred[tid] = 0.f;
    __syncthreads();
    if ((lane >> 2) == 0) {             // lanes 0..3 per warp
        #pragma unroll
        for (int nc = 0; nc < 2; nc++)
            #pragma unroll
            for (int n8 = 0; n8 < 2; n8++)
                #pragma unroll
                for (int j = 0; j < 2; j++) {
                    const int col = cb + nc * 16 + n8 * 8 + j;
                    atomicAdd(&sred[col],      ls[nc][n8][j]);
                    atomicAdd(&sred[64 + col], lq[nc][n8][j]);
                }
    }
    __syncthreads();
    if (tid < 128) atomicAdd(&g_stats[tid], sred[tid]);
}

// ----------------------------------------------------------------------------
// Kernel 4: finalize BN scale/shift
// ----------------------------------------------------------------------------
__global__ void finalize_kernel(const float* __restrict__ gamma,
                                const float* __restrict__ beta) {
    int c = threadIdx.x;
    if (c < COUT) {
        float mean = g_stats[c] * (1.f / (float)NPTS);
        float var  = g_stats[64 + c] * (1.f / (float)NPTS) - mean * mean;
        float sc   = gamma[c] * rsqrtf(var + EPSV);
        g_stats[128 + c] = sc;
        g_stats[192 + c] = beta[c] - mean * sc;
    }
}

// ----------------------------------------------------------------------------
// Kernel 5: apply BN + ReLU
// ----------------------------------------------------------------------------
__global__ void apply_kernel(float* __restrict__ out) {
    int i = blockIdx.x * blockDim.x + threadIdx.x;      // float4 index, exact grid
    float4 v = *((const float4*)g_conv + i);
    int cq = (i & 15) * 4;
    float4 sc = *(const float4*)(&g_stats[128 + cq]);
    float4 sh = *(const float4*)(&g_stats[192 + cq]);
    v.x = fmaxf(fmaf(v.x, sc.x, sh.x), 0.f);
    v.y = fmaxf(fmaf(v.y, sc.y, sh.y), 0.f);
    v.z = fmaxf(fmaf(v.z, sc.z, sh.z), 0.f);
    v.w = fmaxf(fmaf(v.w, sc.w, sh.w), 0.f);
    ((float4*)out)[i] = v;
}

// ----------------------------------------------------------------------------
// Launch
// ----------------------------------------------------------------------------
extern "C" void kernel_launch(void* const* d_in, const int* in_sizes, int n_in,
                              void* d_out, int out_size) {
    const float* feat  = (const float*)d_in[0];
    const int*   nbr   = (const int*)d_in[1];
    const float* w     = (const float*)d_in[2];
    const float* gamma = (const float*)d_in[3];
    const float* beta  = (const float*)d_in[4];
    float*       out   = (float*)d_out;
    (void)in_sizes; (void)n_in; (void)out_size;

    cudaFuncSetAttribute(conv_kernel,
                         cudaFuncAttributeMaxDynamicSharedMemorySize, CONV_SMEM);

    {
        int total4 = (NPTS + 1) * 16;
        prep_feat_kernel<<<(total4 + 255) / 256, 256>>>(feat);
    }
    prep_w_kernel<<<KOFF + 1, 256>>>(w);
    conv_kernel<<<NTILES, 256, CONV_SMEM>>>(nbr);
    finalize_kernel<<<1, 64>>>(gamma, beta);
    apply_kernel<<<(NPTS * COUT / 4) / 256, 256>>>(out);
}

// round 8
// speedup vs baseline: 3.4034x; 1.0561x over previous
#include <cuda_runtime.h>
#include <cuda_fp16.h>
#include <cstdint>

// ----------------------------------------------------------------------------
// Problem constants
// ----------------------------------------------------------------------------
#define NPTS   262144
#define KOFF   27
#define CIN    64
#define COUT   64
#define TILE_M 128
#define NTILES (NPTS / TILE_M)   // 2048
#define EPSV   1e-5f

// ----------------------------------------------------------------------------
// Device scratch (static allocations only)
// ----------------------------------------------------------------------------
// Features as fp16, 128B per row; extra zero row at index NPTS.
__device__ __half g_feat[(size_t)(NPTS + 1) * 64];
// Weights, transposed: [k][co][ci] fp16
__device__ __half g_wt[(size_t)KOFF * COUT * CIN];
__device__ float  g_conv[(size_t)NPTS * COUT];   // conv output before BN
__device__ float  g_stats[256];                  // [0:64) sum [64:128) sumsq
                                                 // [128:192) scale [192:256) shift

// ----------------------------------------------------------------------------
// Helpers
// ----------------------------------------------------------------------------
__device__ __forceinline__ uint32_t smem_u32(const void* p) {
    uint32_t a;
    asm("{ .reg .u64 t; cvta.to.shared.u64 t, %1; cvt.u32.u64 %0, t; }"
        : "=r"(a) : "l"(p));
    return a;
}

__device__ __forceinline__ void ldsm4(uint32_t* r, uint32_t addr) {
    asm volatile("ldmatrix.sync.aligned.m8n8.x4.shared.b16 {%0,%1,%2,%3}, [%4];"
                 : "=r"(r[0]), "=r"(r[1]), "=r"(r[2]), "=r"(r[3]) : "r"(addr));
}

__device__ __forceinline__ void mma16816(float* c, const uint32_t* a,
                                         uint32_t b0, uint32_t b1) {
    asm volatile(
        "mma.sync.aligned.m16n8k16.row.col.f32.f16.f16.f32 "
        "{%0,%1,%2,%3}, {%4,%5,%6,%7}, {%8,%9}, {%0,%1,%2,%3};"
        : "+f"(c[0]), "+f"(c[1]), "+f"(c[2]), "+f"(c[3])
        : "r"(a[0]), "r"(a[1]), "r"(a[2]), "r"(a[3]), "r"(b0), "r"(b1));
}

__device__ __forceinline__ void cp16(uint32_t smem_dst, const void* gsrc) {
    asm volatile("cp.async.cg.shared.global [%0], [%1], 16;"
                 :: "r"(smem_dst), "l"(gsrc));
}

// ----------------------------------------------------------------------------
// Kernel 1: features f32 -> fp16, 128B rows; zero pad row at index NPTS
// ----------------------------------------------------------------------------
__global__ void prep_feat_kernel(const float* __restrict__ feat) {
    const int total4 = (NPTS + 1) * 16;          // float4 count
    int i = blockIdx.x * blockDim.x + threadIdx.x;
    if (i >= total4) return;
    float4 v;
    if (i < NPTS * 16) v = ((const float4*)feat)[i];
    else               v = make_float4(0.f, 0.f, 0.f, 0.f);

    int row = i >> 4, c4 = i & 15;
    __half2* hi = (__half2*)(g_feat + (size_t)row * 64 + c4 * 4);
    hi[0] = __halves2half2(__float2half_rn(v.x), __float2half_rn(v.y));
    hi[1] = __halves2half2(__float2half_rn(v.z), __float2half_rn(v.w));
}

// ----------------------------------------------------------------------------
// Kernel 2: weights [k][ci][co] -> [k][co][ci] fp16; zero stats accums
// ----------------------------------------------------------------------------
__global__ void prep_w_kernel(const float* __restrict__ w) {
    int k = blockIdx.x;
    if (k == KOFF) {
        if (threadIdx.x < 128) g_stats[threadIdx.x] = 0.f;
        return;
    }
    for (int idx = threadIdx.x; idx < CIN * COUT; idx += blockDim.x) {
        int ci = idx / COUT, co = idx % COUT;
        float f = w[(size_t)k * CIN * COUT + idx];
        g_wt[(size_t)k * COUT * CIN + (size_t)co * CIN + ci] = __float2half_rn(f);
    }
}

// ----------------------------------------------------------------------------
// Kernel 3: 3-stage cp.async pipeline, 3 CTAs/SM.
// 2048 CTAs x 256 threads (8 warps, warp grid 4M x 2N, 32x32 per warp).
// Stage (24KB): A[128][128B] | W[64][128B], XOR-quad swizzle.
// Iter k: wait fill(k) -> barrier (retires MMA(k-1)) -> issue fill(k+2)
// (targets MMA(k-1)'s buffer: safe) -> MMA(k).
// ----------------------------------------------------------------------------
#define STAGE    24576
#define W_OFF    16384
#define NSTAGE   3
#define CONV_SMEM (NSTAGE * STAGE)

__device__ __forceinline__ void fill_stage(uint32_t buf, int g, int k,
                                           int tid) {
    // A: thread covers row tid>>1, half tid&1 (4 x int4 = 64B)
    const int row  = tid >> 1;
    const int half = tid & 1;
    const uint32_t key = (uint32_t)(row & 7);
    const int4* fr = (const int4*)g_feat + (size_t)g * 8 + half * 4;
    #pragma unroll
    for (int q = 0; q < 4; q++) {
        uint32_t qq = (uint32_t)(half * 4 + q);
        cp16(buf + (uint32_t)row * 128 + ((qq ^ key) << 4), fr + q);
    }
    // W: 512 int4, 2 per thread
    const int4* wsrc = (const int4*)(g_wt + (size_t)k * COUT * CIN);
    #pragma unroll
    for (int j = 0; j < 2; j++) {
        int lin = tid + j * 256;
        int rr = lin >> 3, q = lin & 7;
        cp16(buf + W_OFF + rr * 128 + (((uint32_t)q ^ (uint32_t)(rr & 7)) << 4),
             wsrc + lin);
    }
    asm volatile("cp.async.commit_group;");
}

__global__ void __launch_bounds__(256, 3) conv_kernel(const int* __restrict__ nbr) {
    extern __shared__ char smem[];
    const uint32_t sb  = smem_u32(smem);
    const int tid  = threadIdx.x;
    const int wid  = tid >> 5;
    const int lane = tid & 31;
    const int wm   = wid >> 1;          // 0..3 -> m base wm*32
    const int wn   = wid & 1;           // n base wn*32
    const int row0 = blockIdx.x * TILE_M;

    float c[2][2][2][4];                // [mt][nc][n8][frag]
    #pragma unroll
    for (int a = 0; a < 2; a++)
        #pragma unroll
        for (int b = 0; b < 2; b++)
            #pragma unroll
            for (int d = 0; d < 2; d++)
                #pragma unroll
                for (int j = 0; j < 4; j++) c[a][b][d][j] = 0.f;

    const int* idxp = nbr + row0 + (tid >> 1);  // this thread's gather row

    // --- prologue: fill stages for k = 0,1 ---
    {
        int g0 = __ldg(idxp);
        int g1 = __ldg(idxp + NPTS);
        fill_stage(sb,         g0, 0, tid);
        fill_stage(sb + STAGE, g1, 1, tid);
    }
    int g_next = __ldg(idxp + (size_t)2 * NPTS);   // idx for k=2

    // ldmatrix invariants
    const uint32_t arow  = (uint32_t)(wm * 32 + (lane & 15));
    const uint32_t aswz  = (uint32_t)((lane & 15) & 7);
    const uint32_t ahalf = (uint32_t)(lane >> 4);
    const uint32_t brow  = (uint32_t)(wn * 32 + (lane & 7) + ((lane >> 4) << 3));
    const uint32_t bswz  = (uint32_t)(lane & 7);
    const uint32_t bhalf = (uint32_t)((lane >> 3) & 1);

    int cur = 0;                        // k % 3
    int nxt2 = 2;                       // (k+2) % 3
    for (int k = 0; k < KOFF; k++) {
        // fill(k) done (per-thread), then barrier: visibility + retire MMA(k-1)
        if (k < KOFF - 1) asm volatile("cp.async.wait_group 1;");
        else              asm volatile("cp.async.wait_group 0;");
        __syncthreads();

        if (k + 2 < KOFF) {
            fill_stage(sb + (uint32_t)nxt2 * STAGE, g_next, k + 2, tid);
            if (k + 3 < KOFF) g_next = __ldg(idxp + (size_t)(k + 3) * NPTS);
        }

        const uint32_t A0 = sb + (uint32_t)cur * STAGE;
        const uint32_t WH = A0 + W_OFF;

        #pragma unroll
        for (int ks = 0; ks < 4; ks++) {
            const uint32_t aoff = (((uint32_t)(2 * ks) + ahalf) ^ aswz) << 4;
            uint32_t ah[2][4];
            #pragma unroll
            for (int mt = 0; mt < 2; mt++)
                ldsm4(ah[mt], A0 + (arow + mt * 16) * 128 + aoff);
            const uint32_t boff = (((uint32_t)(2 * ks) + bhalf) ^ bswz) << 4;
            #pragma unroll
            for (int nc = 0; nc < 2; nc++) {
                uint32_t bh[4];
                ldsm4(bh, WH + (brow + nc * 16) * 128 + boff);
                #pragma unroll
                for (int mt = 0; mt < 2; mt++) {
                    mma16816(c[mt][nc][0], ah[mt], bh[0], bh[1]);
                    mma16816(c[mt][nc][1], ah[mt], bh[2], bh[3]);
                }
            }
        }
        cur  = (cur  == 2) ? 0 : cur + 1;
        nxt2 = (nxt2 == 2) ? 0 : nxt2 + 1;
        // no trailing barrier: next iteration's barrier retires these MMAs
    }

    // --- epilogue: write 128x64 fp32 tile + per-channel partial stats ---
    const int r0 = row0 + wm * 32 + (lane >> 2);
    const int cb = wn * 32 + (lane & 3) * 2;
    float ls[2][2][2], lq[2][2][2];     // [nc][n8][j] sums / sumsqs
    #pragma unroll
    for (int nc = 0; nc < 2; nc++)
        #pragma unroll
        for (int n8 = 0; n8 < 2; n8++)
            #pragma unroll
            for (int j = 0; j < 2; j++) { ls[nc][n8][j] = 0.f; lq[nc][n8][j] = 0.f; }

    #pragma unroll
    for (int mt = 0; mt < 2; mt++) {
        const int r = r0 + mt * 16;
        #pragma unroll
        for (int nc = 0; nc < 2; nc++) {
            #pragma unroll
            for (int n8 = 0; n8 < 2; n8++) {
                const int col = cb + nc * 16 + n8 * 8;
                float v0 = c[mt][nc][n8][0], v1 = c[mt][nc][n8][1];
                float v2 = c[mt][nc][n8][2], v3 = c[mt][nc][n8][3];
                *(float2*)(g_conv + (size_t)r * COUT + col)       = make_float2(v0, v1);
                *(float2*)(g_conv + (size_t)(r + 8) * COUT + col) = make_float2(v2, v3);
                ls[nc][n8][0] += v0 + v2;  lq[nc][n8][0] += v0 * v0 + v2 * v2;
                ls[nc][n8][1] += v1 + v3;  lq[nc][n8][1] += v1 * v1 + v3 * v3;
            }
        }
    }

    // reduce across the 8 lanes sharing (lane & 3)
    #pragma unroll
    for (int nc = 0; nc < 2; nc++)
        #pragma unroll
        for (int n8 = 0; n8 < 2; n8++)
            #pragma unroll
            for (int j = 0; j < 2; j++) {
                float s = ls[nc][n8][j], q = lq[nc][n8][j];
                #pragma unroll
                for (int sh = 4; sh <= 16; sh <<= 1) {
                    s += __shfl_xor_sync(0xFFFFFFFFu, s, sh);
                    q += __shfl_xor_sync(0xFFFFFFFFu, q, sh);
                }
                ls[nc][n8][j] = s; lq[nc][n8][j] = q;
            }

    float* sred = (float*)smem;         // reuse stage 0 (all MMA reads done)
    __syncthreads();
    if (tid < 128) sred[tid] = 0.f;
    __syncthreads();
    if ((lane >> 2) == 0) {             // lanes 0..3 per warp
        #pragma unroll
        for (int nc = 0; nc < 2; nc++)
            #pragma unroll
            for (int n8 = 0; n8 < 2; n8++)
                #pragma unroll
                for (int j = 0; j < 2; j++) {
                    const int col = cb + nc * 16 + n8 * 8 + j;
                    atomicAdd(&sred[col],      ls[nc][n8][j]);
                    atomicAdd(&sred[64 + col], lq[nc][n8][j]);
                }
    }
    __syncthreads();
    if (tid < 128) atomicAdd(&g_stats[tid], sred[tid]);
}

// ----------------------------------------------------------------------------
// Kernel 4: finalize BN scale/shift
// ----------------------------------------------------------------------------
__global__ void finalize_kernel(const float* __restrict__ gamma,
                                const float* __restrict__ beta) {
    int c = threadIdx.x;
    if (c < COUT) {
        float mean = g_stats[c] * (1.f / (float)NPTS);
        float var  = g_stats[64 + c] * (1.f / (float)NPTS) - mean * mean;
        float sc   = gamma[c] * rsqrtf(var + EPSV);
        g_stats[128 + c] = sc;
        g_stats[192 + c] = beta[c] - mean * sc;
    }
}

// ----------------------------------------------------------------------------
// Kernel 5: apply BN + ReLU
// ----------------------------------------------------------------------------
__global__ void apply_kernel(float* __restrict__ out) {
    int i = blockIdx.x * blockDim.x + threadIdx.x;      // float4 index, exact grid
    float4 v = *((const float4*)g_conv + i);
    int cq = (i & 15) * 4;
    float4 sc = *(const float4*)(&g_stats[128 + cq]);
    float4 sh = *(const float4*)(&g_stats[192 + cq]);
    v.x = fmaxf(fmaf(v.x, sc.x, sh.x), 0.f);
    v.y = fmaxf(fmaf(v.y, sc.y, sh.y), 0.f);
    v.z = fmaxf(fmaf(v.z, sc.z, sh.z), 0.f);
    v.w = fmaxf(fmaf(v.w, sc.w, sh.w), 0.f);
    ((float4*)out)[i] = v;
}

// ----------------------------------------------------------------------------
// Launch
// ----------------------------------------------------------------------------
extern "C" void kernel_launch(void* const* d_in, const int* in_sizes, int n_in,
                              void* d_out, int out_size) {
    const float* feat  = (const float*)d_in[0];
    const int*   nbr   = (const int*)d_in[1];
    const float* w     = (const float*)d_in[2];
    const float* gamma = (const float*)d_in[3];
    const float* beta  = (const float*)d_in[4];
    float*       out   = (float*)d_out;
    (void)in_sizes; (void)n_in; (void)out_size;

    cudaFuncSetAttribute(conv_kernel,
                         cudaFuncAttributeMaxDynamicSharedMemorySize, CONV_SMEM);

    {
        int total4 = (NPTS + 1) * 16;
        prep_feat_kernel<<<(total4 + 255) / 256, 256>>>(feat);
    }
    prep_w_kernel<<<KOFF + 1, 256>>>(w);
    conv_kernel<<<NTILES, 256, CONV_SMEM>>>(nbr);
    finalize_kernel<<<1, 64>>>(gamma, beta);
    apply_kernel<<<(NPTS * COUT / 4) / 256, 256>>>(out);
}

// round 9
// speedup vs baseline: 3.4463x; 1.0126x over previous
#include <cuda_runtime.h>
#include <cuda_fp16.h>
#include <cstdint>

// ----------------------------------------------------------------------------
// Problem constants
// ----------------------------------------------------------------------------
#define NPTS   262144
#define KOFF   27
#define CIN    64
#define COUT   64
#define TILE_M 128
#define NTILES (NPTS / TILE_M)   // 2048
#define EPSV   1e-5f

// ----------------------------------------------------------------------------
// Device scratch (static allocations only)
// ----------------------------------------------------------------------------
// Features as fp16, 128B per row; extra zero row at index NPTS.
__device__ __half g_feat[(size_t)(NPTS + 1) * 64];
// Weights, transposed: [k][co][ci] fp16
__device__ __half g_wt[(size_t)KOFF * COUT * CIN];
__device__ __half g_convh[(size_t)NPTS * COUT];  // conv output (fp16 scratch)
__device__ float  g_stats[128];                  // [0:64) sum [64:128) sumsq

// ----------------------------------------------------------------------------
// Helpers
// ----------------------------------------------------------------------------
__device__ __forceinline__ uint32_t smem_u32(const void* p) {
    uint32_t a;
    asm("{ .reg .u64 t; cvta.to.shared.u64 t, %1; cvt.u32.u64 %0, t; }"
        : "=r"(a) : "l"(p));
    return a;
}

__device__ __forceinline__ void ldsm4(uint32_t* r, uint32_t addr) {
    asm volatile("ldmatrix.sync.aligned.m8n8.x4.shared.b16 {%0,%1,%2,%3}, [%4];"
                 : "=r"(r[0]), "=r"(r[1]), "=r"(r[2]), "=r"(r[3]) : "r"(addr));
}

__device__ __forceinline__ void mma16816(float* c, const uint32_t* a,
                                         uint32_t b0, uint32_t b1) {
    asm volatile(
        "mma.sync.aligned.m16n8k16.row.col.f32.f16.f16.f32 "
        "{%0,%1,%2,%3}, {%4,%5,%6,%7}, {%8,%9}, {%0,%1,%2,%3};"
        : "+f"(c[0]), "+f"(c[1]), "+f"(c[2]), "+f"(c[3])
        : "r"(a[0]), "r"(a[1]), "r"(a[2]), "r"(a[3]), "r"(b0), "r"(b1));
}

__device__ __forceinline__ void cp16(uint32_t smem_dst, const void* gsrc) {
    asm volatile("cp.async.cg.shared.global [%0], [%1], 16;"
                 :: "r"(smem_dst), "l"(gsrc));
}

// ----------------------------------------------------------------------------
// Kernel 1 (fused prep): features -> fp16 table, weights -> [k][co][ci] fp16,
// stats accumulators -> 0.   Grid = FEAT_BLOCKS + KOFF + 1.
// ----------------------------------------------------------------------------
#define FEAT_TOTAL4 ((NPTS + 1) * 16)
#define FEAT_BLOCKS ((FEAT_TOTAL4 + 255) / 256)   // 16385

__global__ void prep_kernel(const float* __restrict__ feat,
                            const float* __restrict__ w) {
    const int b = blockIdx.x;
    if (b < FEAT_BLOCKS) {
        int i = b * 256 + threadIdx.x;
        if (i >= FEAT_TOTAL4) return;
        float4 v;
        if (i < NPTS * 16) v = ((const float4*)feat)[i];
        else               v = make_float4(0.f, 0.f, 0.f, 0.f);
        int row = i >> 4, c4 = i & 15;
        __half2* hi = (__half2*)(g_feat + (size_t)row * 64 + c4 * 4);
        hi[0] = __halves2half2(__float2half_rn(v.x), __float2half_rn(v.y));
        hi[1] = __halves2half2(__float2half_rn(v.z), __float2half_rn(v.w));
    } else if (b < FEAT_BLOCKS + KOFF) {
        int k = b - FEAT_BLOCKS;
        for (int idx = threadIdx.x; idx < CIN * COUT; idx += 256) {
            int ci = idx / COUT, co = idx % COUT;
            float f = w[(size_t)k * CIN * COUT + idx];
            g_wt[(size_t)k * COUT * CIN + (size_t)co * CIN + ci] = __float2half_rn(f);
        }
    } else {
        if (threadIdx.x < 128) g_stats[threadIdx.x] = 0.f;
    }
}

// ----------------------------------------------------------------------------
// Kernel 2: 3-stage cp.async pipeline, 3 CTAs/SM.
// 2048 CTAs x 256 threads (8 warps, warp grid 4M x 2N, 32x32 per warp).
// Stage (24KB): A[128][128B] | W[64][128B], XOR-quad swizzle.
// Iter k: wait fill(k) -> barrier (retires MMA(k-1)) -> issue fill(k+2)
// (targets MMA(k-1)'s buffer: safe) -> MMA(k).
// ----------------------------------------------------------------------------
#define STAGE    24576
#define W_OFF    16384
#define NSTAGE   3
#define CONV_SMEM (NSTAGE * STAGE)

__device__ __forceinline__ void fill_stage(uint32_t buf, int g, int k,
                                           int tid) {
    // A: thread covers row tid>>1, half tid&1 (4 x int4 = 64B)
    const int row  = tid >> 1;
    const int half = tid & 1;
    const uint32_t key = (uint32_t)(row & 7);
    const int4* fr = (const int4*)g_feat + (size_t)g * 8 + half * 4;
    #pragma unroll
    for (int q = 0; q < 4; q++) {
        uint32_t qq = (uint32_t)(half * 4 + q);
        cp16(buf + (uint32_t)row * 128 + ((qq ^ key) << 4), fr + q);
    }
    // W: 512 int4, 2 per thread
    const int4* wsrc = (const int4*)(g_wt + (size_t)k * COUT * CIN);
    #pragma unroll
    for (int j = 0; j < 2; j++) {
        int lin = tid + j * 256;
        int rr = lin >> 3, q = lin & 7;
        cp16(buf + W_OFF + rr * 128 + (((uint32_t)q ^ (uint32_t)(rr & 7)) << 4),
             wsrc + lin);
    }
    asm volatile("cp.async.commit_group;");
}

__global__ void __launch_bounds__(256, 3) conv_kernel(const int* __restrict__ nbr) {
    extern __shared__ char smem[];
    const uint32_t sb  = smem_u32(smem);
    const int tid  = threadIdx.x;
    const int wid  = tid >> 5;
    const int lane = tid & 31;
    const int wm   = wid >> 1;          // 0..3 -> m base wm*32
    const int wn   = wid & 1;           // n base wn*32
    const int row0 = blockIdx.x * TILE_M;

    float c[2][2][2][4];                // [mt][nc][n8][frag]
    #pragma unroll
    for (int a = 0; a < 2; a++)
        #pragma unroll
        for (int b = 0; b < 2; b++)
            #pragma unroll
            for (int d = 0; d < 2; d++)
                #pragma unroll
                for (int j = 0; j < 4; j++) c[a][b][d][j] = 0.f;

    const int* idxp = nbr + row0 + (tid >> 1);  // this thread's gather row

    // --- prologue: fill stages for k = 0,1 ---
    {
        int g0 = __ldg(idxp);
        int g1 = __ldg(idxp + NPTS);
        fill_stage(sb,         g0, 0, tid);
        fill_stage(sb + STAGE, g1, 1, tid);
    }
    int g_next = __ldg(idxp + (size_t)2 * NPTS);   // idx for k=2

    // ldmatrix invariants
    const uint32_t arow  = (uint32_t)(wm * 32 + (lane & 15));
    const uint32_t aswz  = (uint32_t)((lane & 15) & 7);
    const uint32_t ahalf = (uint32_t)(lane >> 4);
    const uint32_t brow  = (uint32_t)(wn * 32 + (lane & 7) + ((lane >> 4) << 3));
    const uint32_t bswz  = (uint32_t)(lane & 7);
    const uint32_t bhalf = (uint32_t)((lane >> 3) & 1);

    int cur = 0;                        // k % 3
    int nxt2 = 2;                       // (k+2) % 3
    for (int k = 0; k < KOFF; k++) {
        // fill(k) done (per-thread), then barrier: visibility + retire MMA(k-1)
        if (k < KOFF - 1) asm volatile("cp.async.wait_group 1;");
        else              asm volatile("cp.async.wait_group 0;");
        __syncthreads();

        if (k + 2 < KOFF) {
            fill_stage(sb + (uint32_t)nxt2 * STAGE, g_next, k + 2, tid);
            if (k + 3 < KOFF) g_next = __ldg(idxp + (size_t)(k + 3) * NPTS);
        }

        const uint32_t A0 = sb + (uint32_t)cur * STAGE;
        const uint32_t WH = A0 + W_OFF;

        #pragma unroll
        for (int ks = 0; ks < 4; ks++) {
            const uint32_t aoff = (((uint32_t)(2 * ks) + ahalf) ^ aswz) << 4;
            uint32_t ah[2][4];
            #pragma unroll
            for (int mt = 0; mt < 2; mt++)
                ldsm4(ah[mt], A0 + (arow + mt * 16) * 128 + aoff);
            const uint32_t boff = (((uint32_t)(2 * ks) + bhalf) ^ bswz) << 4;
            #pragma unroll
            for (int nc = 0; nc < 2; nc++) {
                uint32_t bh[4];
                ldsm4(bh, WH + (brow + nc * 16) * 128 + boff);
                #pragma unroll
                for (int mt = 0; mt < 2; mt++) {
                    mma16816(c[mt][nc][0], ah[mt], bh[0], bh[1]);
                    mma16816(c[mt][nc][1], ah[mt], bh[2], bh[3]);
                }
            }
        }
        cur  = (cur  == 2) ? 0 : cur + 1;
        nxt2 = (nxt2 == 2) ? 0 : nxt2 + 1;
        // no trailing barrier: next iteration's barrier retires these MMAs
    }

    // --- epilogue: write 128x64 fp16 tile + per-channel partial stats ---
    const int r0 = row0 + wm * 32 + (lane >> 2);
    const int cb = wn * 32 + (lane & 3) * 2;
    float ls[2][2][2], lq[2][2][2];     // [nc][n8][j] sums / sumsqs
    #pragma unroll
    for (int nc = 0; nc < 2; nc++)
        #pragma unroll
        for (int n8 = 0; n8 < 2; n8++)
            #pragma unroll
            for (int j = 0; j < 2; j++) { ls[nc][n8][j] = 0.f; lq[nc][n8][j] = 0.f; }

    #pragma unroll
    for (int mt = 0; mt < 2; mt++) {
        const int r = r0 + mt * 16;
        #pragma unroll
        for (int nc = 0; nc < 2; nc++) {
            #pragma unroll
            for (int n8 = 0; n8 < 2; n8++) {
                const int col = cb + nc * 16 + n8 * 8;
                float v0 = c[mt][nc][n8][0], v1 = c[mt][nc][n8][1];
                float v2 = c[mt][nc][n8][2], v3 = c[mt][nc][n8][3];
                *(__half2*)(g_convh + (size_t)r * COUT + col) =
                    __floats2half2_rn(v0, v1);
                *(__half2*)(g_convh + (size_t)(r + 8) * COUT + col) =
                    __floats2half2_rn(v2, v3);
                ls[nc][n8][0] += v0 + v2;  lq[nc][n8][0] += v0 * v0 + v2 * v2;
                ls[nc][n8][1] += v1 + v3;  lq[nc][n8][1] += v1 * v1 + v3 * v3;
            }
        }
    }

    // reduce across the 8 lanes sharing (lane & 3)
    #pragma unroll
    for (int nc = 0; nc < 2; nc++)
        #pragma unroll
        for (int n8 = 0; n8 < 2; n8++)
            #pragma unroll
            for (int j = 0; j < 2; j++) {
                float s = ls[nc][n8][j], q = lq[nc][n8][j];
                #pragma unroll
                for (int sh = 4; sh <= 16; sh <<= 1) {
                    s += __shfl_xor_sync(0xFFFFFFFFu, s, sh);
                    q += __shfl_xor_sync(0xFFFFFFFFu, q, sh);
                }
                ls[nc][n8][j] = s; lq[nc][n8][j] = q;
            }

    float* sred = (float*)smem;         // reuse stage 0 (all MMA reads done)
    __syncthreads();
    if (tid < 128) sred[tid] = 0.f;
    __syncthreads();
    if ((lane >> 2) == 0) {             // lanes 0..3 per warp
        #pragma unroll
        for (int nc = 0; nc < 2; nc++)
            #pragma unroll
            for (int n8 = 0; n8 < 2; n8++)
                #pragma unroll
                for (int j = 0; j < 2; j++) {
                    const int col = cb + nc * 16 + n8 * 8 + j;
                    atomicAdd(&sred[col],      ls[nc][n8][j]);
                    atomicAdd(&sred[64 + col], lq[nc][n8][j]);
                }
    }
    __syncthreads();
    if (tid < 128) atomicAdd(&g_stats[tid], sred[tid]);
}

// ----------------------------------------------------------------------------
// Kernel 3: apply BN + ReLU (per-block recompute of scale/shift from g_stats)
// ----------------------------------------------------------------------------
__global__ void apply_kernel(const float* __restrict__ gamma,
                             const float* __restrict__ beta,
                             float* __restrict__ out) {
    __shared__ float ssc[64], ssh[64];
    const int t = threadIdx.x;
    if (t < 64) {
        float mean = g_stats[t] * (1.f / (float)NPTS);
        float var  = g_stats[64 + t] * (1.f / (float)NPTS) - mean * mean;
        float sc   = gamma[t] * rsqrtf(var + EPSV);
        ssc[t] = sc;
        ssh[t] = beta[t] - mean * sc;
    }
    __syncthreads();

    const int i = blockIdx.x * 256 + t;          // float4 output index, exact grid
    uint2 hv = ((const uint2*)g_convh)[i];       // 4 fp16 values
    float2 f0 = __half22float2(*(__half2*)&hv.x);
    float2 f1 = __half22float2(*(__half2*)&hv.y);
    const int c0 = (i & 15) * 4;
    float4 r;
    r.x = fmaxf(fmaf(f0.x, ssc[c0],     ssh[c0]),     0.f);
    r.y = fmaxf(fmaf(f0.y, ssc[c0 + 1], ssh[c0 + 1]), 0.f);
    r.z = fmaxf(fmaf(f1.x, ssc[c0 + 2], ssh[c0 + 2]), 0.f);
    r.w = fmaxf(fmaf(f1.y, ssc[c0 + 3], ssh[c0 + 3]), 0.f);
    ((float4*)out)[i] = r;
}

// ----------------------------------------------------------------------------
// Launch
// ----------------------------------------------------------------------------
extern "C" void kernel_launch(void* const* d_in, const int* in_sizes, int n_in,
                              void* d_out, int out_size) {
    const float* feat  = (const float*)d_in[0];
    const int*   nbr   = (const int*)d_in[1];
    const float* w     = (const float*)d_in[2];
    const float* gamma = (const float*)d_in[3];
    const float* beta  = (const float*)d_in[4];
    float*       out   = (float*)d_out;
    (void)in_sizes; (void)n_in; (void)out_size;

    cudaFuncSetAttribute(conv_kernel,
                         cudaFuncAttributeMaxDynamicSharedMemorySize, CONV_SMEM);

    prep_kernel<<<FEAT_BLOCKS + KOFF + 1, 256>>>(feat, w);
    conv_kernel<<<NTILES, 256, CONV_SMEM>>>(nbr);
    apply_kernel<<<(NPTS * COUT / 4) / 256, 256>>>(gamma, beta, out);
}

// round 10
// speedup vs baseline: 3.4986x; 1.0152x over previous
#include <cuda_runtime.h>
#include <cuda_fp16.h>
#include <cstdint>

// ----------------------------------------------------------------------------
// Problem constants
// ----------------------------------------------------------------------------
#define NPTS   262144
#define KOFF   27
#define CIN    64
#define COUT   64
#define TILE_M 128
#define NTILES (NPTS / TILE_M)   // 2048
#define EPSV   1e-5f

// ----------------------------------------------------------------------------
// Device scratch (static allocations only)
// ----------------------------------------------------------------------------
// Features as fp16, 128B per row; extra zero row at index NPTS.
__device__ __half g_feat[(size_t)(NPTS + 1) * 64];
// Weights, transposed: [k][co][ci] fp16
__device__ __half g_wt[(size_t)KOFF * COUT * CIN];
__device__ __half g_convh[(size_t)NPTS * COUT];  // conv output (fp16 scratch)
__device__ float  g_stats[128];                  // [0:64) sum [64:128) sumsq

// ----------------------------------------------------------------------------
// Helpers
// ----------------------------------------------------------------------------
__device__ __forceinline__ uint32_t smem_u32(const void* p) {
    uint32_t a;
    asm("{ .reg .u64 t; cvta.to.shared.u64 t, %1; cvt.u32.u64 %0, t; }"
        : "=r"(a) : "l"(p));
    return a;
}

__device__ __forceinline__ void ldsm4(uint32_t* r, uint32_t addr) {
    asm volatile("ldmatrix.sync.aligned.m8n8.x4.shared.b16 {%0,%1,%2,%3}, [%4];"
                 : "=r"(r[0]), "=r"(r[1]), "=r"(r[2]), "=r"(r[3]) : "r"(addr));
}

__device__ __forceinline__ void mma16816(float* c, const uint32_t* a,
                                         uint32_t b0, uint32_t b1) {
    asm volatile(
        "mma.sync.aligned.m16n8k16.row.col.f32.f16.f16.f32 "
        "{%0,%1,%2,%3}, {%4,%5,%6,%7}, {%8,%9}, {%0,%1,%2,%3};"
        : "+f"(c[0]), "+f"(c[1]), "+f"(c[2]), "+f"(c[3])
        : "r"(a[0]), "r"(a[1]), "r"(a[2]), "r"(a[3]), "r"(b0), "r"(b1));
}

__device__ __forceinline__ void cp16(uint32_t smem_dst, const void* gsrc) {
    asm volatile("cp.async.cg.shared.global [%0], [%1], 16;"
                 :: "r"(smem_dst), "l"(gsrc));
}

// ----------------------------------------------------------------------------
// Kernel 1 (fused prep): features -> fp16 table (4-way ILP), weights ->
// [k][co][ci] fp16, stats accumulators -> 0.
// Feature part: group = 8 floats -> 16B fp16 store.  Each thread handles 4
// groups (4 independent 32B loads in flight).
// ----------------------------------------------------------------------------
#define FEAT_TOTAL8  ((NPTS + 1) * 8)                      // 2097160 groups
#define FEAT_BLOCKS  ((FEAT_TOTAL8 + 1023) / 1024)         // 2049

__global__ void prep_kernel(const float* __restrict__ feat,
                            const float* __restrict__ w) {
    const int b = blockIdx.x;
    if (b < FEAT_BLOCKS) {
        const int base = b * 1024 + threadIdx.x;
        #pragma unroll
        for (int j = 0; j < 4; j++) {
            int g = base + j * 256;                 // group of 8 floats
            if (g >= FEAT_TOTAL8) break;
            float4 v0, v1;
            if (g < NPTS * 8) {
                v0 = ((const float4*)feat)[g * 2];
                v1 = ((const float4*)feat)[g * 2 + 1];
            } else {
                v0 = make_float4(0.f, 0.f, 0.f, 0.f);
                v1 = v0;
            }
            uint4 o;
            ((__half2*)&o)[0] = __floats2half2_rn(v0.x, v0.y);
            ((__half2*)&o)[1] = __floats2half2_rn(v0.z, v0.w);
            ((__half2*)&o)[2] = __floats2half2_rn(v1.x, v1.y);
            ((__half2*)&o)[3] = __floats2half2_rn(v1.z, v1.w);
            *(uint4*)(g_feat + (size_t)g * 8) = o;
        }
    } else if (b < FEAT_BLOCKS + KOFF) {
        int k = b - FEAT_BLOCKS;
        for (int idx = threadIdx.x; idx < CIN * COUT; idx += 256) {
            int ci = idx / COUT, co = idx % COUT;
            float f = w[(size_t)k * CIN * COUT + idx];
            g_wt[(size_t)k * COUT * CIN + (size_t)co * CIN + ci] = __float2half_rn(f);
        }
    } else {
        if (threadIdx.x < 128) g_stats[threadIdx.x] = 0.f;
    }
}

// ----------------------------------------------------------------------------
// Kernel 2: 3-stage cp.async pipeline, 3 CTAs/SM.
// 2048 CTAs x 256 threads (8 warps, warp grid 4M x 2N, 32x32 per warp).
// Stage (24KB): A[128][128B] | W[64][128B], XOR-quad swizzle.
// Iter k: wait fill(k) -> barrier (retires MMA(k-1)) -> issue fill(k+2)
// (targets MMA(k-1)'s buffer: safe) -> MMA(k).
// ----------------------------------------------------------------------------
#define STAGE    24576
#define W_OFF    16384
#define NSTAGE   3
#define CONV_SMEM (NSTAGE * STAGE)

__device__ __forceinline__ void fill_stage(uint32_t buf, int g, int k,
                                           int tid) {
    // A: thread covers row tid>>1, half tid&1 (4 x int4 = 64B)
    const int row  = tid >> 1;
    const int half = tid & 1;
    const uint32_t key = (uint32_t)(row & 7);
    const int4* fr = (const int4*)g_feat + (size_t)g * 8 + half * 4;
    #pragma unroll
    for (int q = 0; q < 4; q++) {
        uint32_t qq = (uint32_t)(half * 4 + q);
        cp16(buf + (uint32_t)row * 128 + ((qq ^ key) << 4), fr + q);
    }
    // W: 512 int4, 2 per thread
    const int4* wsrc = (const int4*)(g_wt + (size_t)k * COUT * CIN);
    #pragma unroll
    for (int j = 0; j < 2; j++) {
        int lin = tid + j * 256;
        int rr = lin >> 3, q = lin & 7;
        cp16(buf + W_OFF + rr * 128 + (((uint32_t)q ^ (uint32_t)(rr & 7)) << 4),
             wsrc + lin);
    }
    asm volatile("cp.async.commit_group;");
}

__global__ void __launch_bounds__(256, 3) conv_kernel(const int* __restrict__ nbr) {
    extern __shared__ char smem[];
    const uint32_t sb  = smem_u32(smem);
    const int tid  = threadIdx.x;
    const int wid  = tid >> 5;
    const int lane = tid & 31;
    const int wm   = wid >> 1;          // 0..3 -> m base wm*32
    const int wn   = wid & 1;           // n base wn*32
    const int row0 = blockIdx.x * TILE_M;

    float c[2][2][2][4];                // [mt][nc][n8][frag]
    #pragma unroll
    for (int a = 0; a < 2; a++)
        #pragma unroll
        for (int b = 0; b < 2; b++)
            #pragma unroll
            for (int d = 0; d < 2; d++)
                #pragma unroll
                for (int j = 0; j < 4; j++) c[a][b][d][j] = 0.f;

    const int* idxp = nbr + row0 + (tid >> 1);  // this thread's gather row

    // --- prologue: fill stages for k = 0,1 ---
    {
        int g0 = __ldg(idxp);
        int g1 = __ldg(idxp + NPTS);
        fill_stage(sb,         g0, 0, tid);
        fill_stage(sb + STAGE, g1, 1, tid);
    }
    int g_next = __ldg(idxp + (size_t)2 * NPTS);   // idx for k=2

    // ldmatrix invariants
    const uint32_t arow  = (uint32_t)(wm * 32 + (lane & 15));
    const uint32_t aswz  = (uint32_t)((lane & 15) & 7);
    const uint32_t ahalf = (uint32_t)(lane >> 4);
    const uint32_t brow  = (uint32_t)(wn * 32 + (lane & 7) + ((lane >> 4) << 3));
    const uint32_t bswz  = (uint32_t)(lane & 7);
    const uint32_t bhalf = (uint32_t)((lane >> 3) & 1);

    int cur = 0;                        // k % 3
    int nxt2 = 2;                       // (k+2) % 3
    for (int k = 0; k < KOFF; k++) {
        // fill(k) done (per-thread), then barrier: visibility + retire MMA(k-1)
        if (k < KOFF - 1) asm volatile("cp.async.wait_group 1;");
        else              asm volatile("cp.async.wait_group 0;");
        __syncthreads();

        if (k + 2 < KOFF) {
            fill_stage(sb + (uint32_t)nxt2 * STAGE, g_next, k + 2, tid);
            if (k + 3 < KOFF) g_next = __ldg(idxp + (size_t)(k + 3) * NPTS);
        }

        const uint32_t A0 = sb + (uint32_t)cur * STAGE;
        const uint32_t WH = A0 + W_OFF;

        #pragma unroll
        for (int ks = 0; ks < 4; ks++) {
            const uint32_t aoff = (((uint32_t)(2 * ks) + ahalf) ^ aswz) << 4;
            uint32_t ah[2][4];
            #pragma unroll
            for (int mt = 0; mt < 2; mt++)
                ldsm4(ah[mt], A0 + (arow + mt * 16) * 128 + aoff);
            const uint32_t boff = (((uint32_t)(2 * ks) + bhalf) ^ bswz) << 4;
            #pragma unroll
            for (int nc = 0; nc < 2; nc++) {
                uint32_t bh[4];
                ldsm4(bh, WH + (brow + nc * 16) * 128 + boff);
                #pragma unroll
                for (int mt = 0; mt < 2; mt++) {
                    mma16816(c[mt][nc][0], ah[mt], bh[0], bh[1]);
                    mma16816(c[mt][nc][1], ah[mt], bh[2], bh[3]);
                }
            }
        }
        cur  = (cur  == 2) ? 0 : cur + 1;
        nxt2 = (nxt2 == 2) ? 0 : nxt2 + 1;
        // no trailing barrier: next iteration's barrier retires these MMAs
    }

    // --- epilogue: write 128x64 fp16 tile + per-channel partial stats ---
    const int r0 = row0 + wm * 32 + (lane >> 2);
    const int cb = wn * 32 + (lane & 3) * 2;
    float ls[2][2][2], lq[2][2][2];     // [nc][n8][j] sums / sumsqs
    #pragma unroll
    for (int nc = 0; nc < 2; nc++)
        #pragma unroll
        for (int n8 = 0; n8 < 2; n8++)
            #pragma unroll
            for (int j = 0; j < 2; j++) { ls[nc][n8][j] = 0.f; lq[nc][n8][j] = 0.f; }

    #pragma unroll
    for (int mt = 0; mt < 2; mt++) {
        const int r = r0 + mt * 16;
        #pragma unroll
        for (int nc = 0; nc < 2; nc++) {
            #pragma unroll
            for (int n8 = 0; n8 < 2; n8++) {
                const int col = cb + nc * 16 + n8 * 8;
                float v0 = c[mt][nc][n8][0], v1 = c[mt][nc][n8][1];
                float v2 = c[mt][nc][n8][2], v3 = c[mt][nc][n8][3];
                *(__half2*)(g_convh + (size_t)r * COUT + col) =
                    __floats2half2_rn(v0, v1);
                *(__half2*)(g_convh + (size_t)(r + 8) * COUT + col) =
                    __floats2half2_rn(v2, v3);
                ls[nc][n8][0] += v0 + v2;  lq[nc][n8][0] += v0 * v0 + v2 * v2;
                ls[nc][n8][1] += v1 + v3;  lq[nc][n8][1] += v1 * v1 + v3 * v3;
            }
        }
    }

    // reduce across the 8 lanes sharing (lane & 3)
    #pragma unroll
    for (int nc = 0; nc < 2; nc++)
        #pragma unroll
        for (int n8 = 0; n8 < 2; n8++)
            #pragma unroll
            for (int j = 0; j < 2; j++) {
                float s = ls[nc][n8][j], q = lq[nc][n8][j];
                #pragma unroll
                for (int sh = 4; sh <= 16; sh <<= 1) {
                    s += __shfl_xor_sync(0xFFFFFFFFu, s, sh);
                    q += __shfl_xor_sync(0xFFFFFFFFu, q, sh);
                }
                ls[nc][n8][j] = s; lq[nc][n8][j] = q;
            }

    float* sred = (float*)smem;         // reuse stage 0 (all MMA reads done)
    __syncthreads();
    if (tid < 128) sred[tid] = 0.f;
    __syncthreads();
    if ((lane >> 2) == 0) {             // lanes 0..3 per warp
        #pragma unroll
        for (int nc = 0; nc < 2; nc++)
            #pragma unroll
            for (int n8 = 0; n8 < 2; n8++)
                #pragma unroll
                for (int j = 0; j < 2; j++) {
                    const int col = cb + nc * 16 + n8 * 8 + j;
                    atomicAdd(&sred[col],      ls[nc][n8][j]);
                    atomicAdd(&sred[64 + col], lq[nc][n8][j]);
                }
    }
    __syncthreads();
    if (tid < 128) atomicAdd(&g_stats[tid], sred[tid]);
}

// ----------------------------------------------------------------------------
// Kernel 3: apply BN + ReLU, 2 float4 outputs per thread (ILP=2).
// Per-block recompute of scale/shift from g_stats.
// ----------------------------------------------------------------------------
__global__ void apply_kernel(const float* __restrict__ gamma,
                             const float* __restrict__ beta,
                             float* __restrict__ out) {
    __shared__ float ssc[64], ssh[64];
    const int t = threadIdx.x;
    if (t < 64) {
        float mean = g_stats[t] * (1.f / (float)NPTS);
        float var  = g_stats[64 + t] * (1.f / (float)NPTS) - mean * mean;
        float sc   = gamma[t] * rsqrtf(var + EPSV);
        ssc[t] = sc;
        ssh[t] = beta[t] - mean * sc;
    }
    __syncthreads();

    const int base = blockIdx.x * 512 + t;       // float4 output index
    #pragma unroll
    for (int j = 0; j < 2; j++) {
        const int i = base + j * 256;            // exact grid, no guard needed
        uint2 hv = ((const uint2*)g_convh)[i];   // 4 fp16 values
        float2 f0 = __half22float2(*(__half2*)&hv.x);
        float2 f1 = __half22float2(*(__half2*)&hv.y);
        const int c0 = (i & 15) * 4;
        float4 r;
        r.x = fmaxf(fmaf(f0.x, ssc[c0],     ssh[c0]),     0.f);
        r.y = fmaxf(fmaf(f0.y, ssc[c0 + 1], ssh[c0 + 1]), 0.f);
        r.z = fmaxf(fmaf(f1.x, ssc[c0 + 2], ssh[c0 + 2]), 0.f);
        r.w = fmaxf(fmaf(f1.y, ssc[c0 + 3], ssh[c0 + 3]), 0.f);
        ((float4*)out)[i] = r;
    }
}

// ----------------------------------------------------------------------------
// Launch
// ----------------------------------------------------------------------------
extern "C" void kernel_launch(void* const* d_in, const int* in_sizes, int n_in,
                              void* d_out, int out_size) {
    const float* feat  = (const float*)d_in[0];
    const int*   nbr   = (const int*)d_in[1];
    const float* w     = (const float*)d_in[2];
    const float* gamma = (const float*)d_in[3];
    const float* beta  = (const float*)d_in[4];
    float*       out   = (float*)d_out;
    (void)in_sizes; (void)n_in; (void)out_size;

    cudaFuncSetAttribute(conv_kernel,
                         cudaFuncAttributeMaxDynamicSharedMemorySize, CONV_SMEM);

    prep_kernel<<<FEAT_BLOCKS + KOFF + 1, 256>>>(feat, w);
    conv_kernel<<<NTILES, 256, CONV_SMEM>>>(nbr);
    apply_kernel<<<(NPTS * COUT / 4) / 512, 256>>>(gamma, beta, out);
}

// round 11
// speedup vs baseline: 3.5156x; 1.0049x over previous
#include <cuda_runtime.h>
#include <cuda_fp16.h>
#include <cstdint>

// ----------------------------------------------------------------------------
// Problem constants
// ----------------------------------------------------------------------------
#define NPTS   262144
#define KOFF   27
#define CIN    64
#define COUT   64
#define TILE_M 128
#define NTILES (NPTS / TILE_M)   // 2048
#define EPSV   1e-5f

// ----------------------------------------------------------------------------
// Device scratch (static allocations only)
// ----------------------------------------------------------------------------
// Features as fp16, 128B per row; extra zero row at index NPTS.
__device__ __half g_feat[(size_t)(NPTS + 1) * 64];
// Weights, transposed: [k][co][ci] fp16
__device__ __half g_wt[(size_t)KOFF * COUT * CIN];
__device__ __half g_convh[(size_t)NPTS * COUT];  // conv output (fp16 scratch)
__device__ float  g_stats[128];                  // [0:64) sum [64:128) sumsq

// ----------------------------------------------------------------------------
// Helpers
// ----------------------------------------------------------------------------
__device__ __forceinline__ uint32_t smem_u32(const void* p) {
    uint32_t a;
    asm("{ .reg .u64 t; cvta.to.shared.u64 t, %1; cvt.u32.u64 %0, t; }"
        : "=r"(a) : "l"(p));
    return a;
}

__device__ __forceinline__ void ldsm4(uint32_t* r, uint32_t addr) {
    asm volatile("ldmatrix.sync.aligned.m8n8.x4.shared.b16 {%0,%1,%2,%3}, [%4];"
                 : "=r"(r[0]), "=r"(r[1]), "=r"(r[2]), "=r"(r[3]) : "r"(addr));
}

__device__ __forceinline__ void mma16816(float* c, const uint32_t* a,
                                         uint32_t b0, uint32_t b1) {
    asm volatile(
        "mma.sync.aligned.m16n8k16.row.col.f32.f16.f16.f32 "
        "{%0,%1,%2,%3}, {%4,%5,%6,%7}, {%8,%9}, {%0,%1,%2,%3};"
        : "+f"(c[0]), "+f"(c[1]), "+f"(c[2]), "+f"(c[3])
        : "r"(a[0]), "r"(a[1]), "r"(a[2]), "r"(a[3]), "r"(b0), "r"(b1));
}

__device__ __forceinline__ void cp16(uint32_t smem_dst, const void* gsrc) {
    asm volatile("cp.async.cg.shared.global [%0], [%1], 16;"
                 :: "r"(smem_dst), "l"(gsrc));
}

// ----------------------------------------------------------------------------
// Kernel 1 (fused prep): features -> fp16 table (exact grid, 4 groups/thread,
// no guards -> 8 batched LDG.128 in flight), weights -> [k][co][ci] fp16,
// stats -> 0 and pad row -> 0.
// Feature blocks: 2048 cover groups [0, NPTS*8) exactly (group = 8 floats).
// ----------------------------------------------------------------------------
#define FEAT_BLOCKS  2048

__global__ void prep_kernel(const float* __restrict__ feat,
                            const float* __restrict__ w) {
    const int b = blockIdx.x;
    if (b < FEAT_BLOCKS) {
        const int base = b * 1024 + threadIdx.x;
        float4 v[4][2];
        #pragma unroll
        for (int j = 0; j < 4; j++) {               // 8 independent LDG.128
            int g = base + j * 256;
            v[j][0] = ((const float4*)feat)[g * 2];
            v[j][1] = ((const float4*)feat)[g * 2 + 1];
        }
        #pragma unroll
        for (int j = 0; j < 4; j++) {
            int g = base + j * 256;
            uint4 o;
            ((__half2*)&o)[0] = __floats2half2_rn(v[j][0].x, v[j][0].y);
            ((__half2*)&o)[1] = __floats2half2_rn(v[j][0].z, v[j][0].w);
            ((__half2*)&o)[2] = __floats2half2_rn(v[j][1].x, v[j][1].y);
            ((__half2*)&o)[3] = __floats2half2_rn(v[j][1].z, v[j][1].w);
            *(uint4*)(g_feat + (size_t)g * 8) = o;
        }
    } else if (b < FEAT_BLOCKS + KOFF) {
        int k = b - FEAT_BLOCKS;
        for (int idx = threadIdx.x; idx < CIN * COUT; idx += 256) {
            int ci = idx / COUT, co = idx % COUT;
            float f = w[(size_t)k * CIN * COUT + idx];
            g_wt[(size_t)k * COUT * CIN + (size_t)co * CIN + ci] = __float2half_rn(f);
        }
    } else {
        if (threadIdx.x < 128) g_stats[threadIdx.x] = 0.f;
        if (threadIdx.x < 8) {                      // zero the pad row (128B)
            uint4 z = make_uint4(0u, 0u, 0u, 0u);
            *(uint4*)(g_feat + (size_t)NPTS * 64 + threadIdx.x * 8) = z;
        }
    }
}

// ----------------------------------------------------------------------------
// Kernel 2: 3-stage cp.async pipeline, 3 CTAs/SM.
// 2048 CTAs x 256 threads (8 warps, warp grid 4M x 2N, 32x32 per warp).
// Stage (24KB): A[128][128B] | W[64][128B], XOR-quad swizzle.
// Iter k: wait fill(k) -> barrier (retires MMA(k-1)) -> issue fill(k+2)
// (targets MMA(k-1)'s buffer: safe) -> MMA(k).
// ----------------------------------------------------------------------------
#define STAGE    24576
#define W_OFF    16384
#define NSTAGE   3
#define CONV_SMEM (NSTAGE * STAGE)

__device__ __forceinline__ void fill_stage(uint32_t buf, int g, int k,
                                           int tid) {
    // A: thread covers row tid>>1, half tid&1 (4 x int4 = 64B)
    const int row  = tid >> 1;
    const int half = tid & 1;
    const uint32_t key = (uint32_t)(row & 7);
    const int4* fr = (const int4*)g_feat + (size_t)g * 8 + half * 4;
    #pragma unroll
    for (int q = 0; q < 4; q++) {
        uint32_t qq = (uint32_t)(half * 4 + q);
        cp16(buf + (uint32_t)row * 128 + ((qq ^ key) << 4), fr + q);
    }
    // W: 512 int4, 2 per thread
    const int4* wsrc = (const int4*)(g_wt + (size_t)k * COUT * CIN);
    #pragma unroll
    for (int j = 0; j < 2; j++) {
        int lin = tid + j * 256;
        int rr = lin >> 3, q = lin & 7;
        cp16(buf + W_OFF + rr * 128 + (((uint32_t)q ^ (uint32_t)(rr & 7)) << 4),
             wsrc + lin);
    }
    asm volatile("cp.async.commit_group;");
}

__global__ void __launch_bounds__(256, 3) conv_kernel(const int* __restrict__ nbr) {
    extern __shared__ char smem[];
    const uint32_t sb  = smem_u32(smem);
    const int tid  = threadIdx.x;
    const int wid  = tid >> 5;
    const int lane = tid & 31;
    const int wm   = wid >> 1;          // 0..3 -> m base wm*32
    const int wn   = wid & 1;           // n base wn*32
    const int row0 = blockIdx.x * TILE_M;

    float c[2][2][2][4];                // [mt][nc][n8][frag]
    #pragma unroll
    for (int a = 0; a < 2; a++)
        #pragma unroll
        for (int b = 0; b < 2; b++)
            #pragma unroll
            for (int d = 0; d < 2; d++)
                #pragma unroll
                for (int j = 0; j < 4; j++) c[a][b][d][j] = 0.f;

    const int* idxp = nbr + row0 + (tid >> 1);  // this thread's gather row

    // --- prologue: fill stages for k = 0,1 ---
    {
        int g0 = __ldg(idxp);
        int g1 = __ldg(idxp + NPTS);
        fill_stage(sb,         g0, 0, tid);
        fill_stage(sb + STAGE, g1, 1, tid);
    }
    int g_next = __ldg(idxp + (size_t)2 * NPTS);   // idx for k=2

    // ldmatrix invariants
    const uint32_t arow  = (uint32_t)(wm * 32 + (lane & 15));
    const uint32_t aswz  = (uint32_t)((lane & 15) & 7);
    const uint32_t ahalf = (uint32_t)(lane >> 4);
    const uint32_t brow  = (uint32_t)(wn * 32 + (lane & 7) + ((lane >> 4) << 3));
    const uint32_t bswz  = (uint32_t)(lane & 7);
    const uint32_t bhalf = (uint32_t)((lane >> 3) & 1);

    int cur = 0;                        // k % 3
    int nxt2 = 2;                       // (k+2) % 3
    for (int k = 0; k < KOFF; k++) {
        // fill(k) done (per-thread), then barrier: visibility + retire MMA(k-1)
        if (k < KOFF - 1) asm volatile("cp.async.wait_group 1;");
        else              asm volatile("cp.async.wait_group 0;");
        __syncthreads();

        if (k + 2 < KOFF) {
            fill_stage(sb + (uint32_t)nxt2 * STAGE, g_next, k + 2, tid);
            if (k + 3 < KOFF) g_next = __ldg(idxp + (size_t)(k + 3) * NPTS);
        }

        const uint32_t A0 = sb + (uint32_t)cur * STAGE;
        const uint32_t WH = A0 + W_OFF;

        #pragma unroll
        for (int ks = 0; ks < 4; ks++) {
            const uint32_t aoff = (((uint32_t)(2 * ks) + ahalf) ^ aswz) << 4;
            uint32_t ah[2][4];
            #pragma unroll
            for (int mt = 0; mt < 2; mt++)
                ldsm4(ah[mt], A0 + (arow + mt * 16) * 128 + aoff);
            const uint32_t boff = (((uint32_t)(2 * ks) + bhalf) ^ bswz) << 4;
            #pragma unroll
            for (int nc = 0; nc < 2; nc++) {
                uint32_t bh[4];
                ldsm4(bh, WH + (brow + nc * 16) * 128 + boff);
                #pragma unroll
                for (int mt = 0; mt < 2; mt++) {
                    mma16816(c[mt][nc][0], ah[mt], bh[0], bh[1]);
                    mma16816(c[mt][nc][1], ah[mt], bh[2], bh[3]);
                }
            }
        }
        cur  = (cur  == 2) ? 0 : cur + 1;
        nxt2 = (nxt2 == 2) ? 0 : nxt2 + 1;
        // no trailing barrier: next iteration's barrier retires these MMAs
    }

    // --- epilogue: write 128x64 fp16 tile + per-channel partial stats ---
    const int r0 = row0 + wm * 32 + (lane >> 2);
    const int cb = wn * 32 + (lane & 3) * 2;
    float ls[2][2][2], lq[2][2][2];     // [nc][n8][j] sums / sumsqs
    #pragma unroll
    for (int nc = 0; nc < 2; nc++)
        #pragma unroll
        for (int n8 = 0; n8 < 2; n8++)
            #pragma unroll
            for (int j = 0; j < 2; j++) { ls[nc][n8][j] = 0.f; lq[nc][n8][j] = 0.f; }

    #pragma unroll
    for (int mt = 0; mt < 2; mt++) {
        const int r = r0 + mt * 16;
        #pragma unroll
        for (int nc = 0; nc < 2; nc++) {
            #pragma unroll
            for (int n8 = 0; n8 < 2; n8++) {
                const int col = cb + nc * 16 + n8 * 8;
                float v0 = c[mt][nc][n8][0], v1 = c[mt][nc][n8][1];
                float v2 = c[mt][nc][n8][2], v3 = c[mt][nc][n8][3];
                *(__half2*)(g_convh + (size_t)r * COUT + col) =
                    __floats2half2_rn(v0, v1);
                *(__half2*)(g_convh + (size_t)(r + 8) * COUT + col) =
                    __floats2half2_rn(v2, v3);
                ls[nc][n8][0] += v0 + v2;  lq[nc][n8][0] += v0 * v0 + v2 * v2;
                ls[nc][n8][1] += v1 + v3;  lq[nc][n8][1] += v1 * v1 + v3 * v3;
            }
        }
    }

    // reduce across the 8 lanes sharing (lane & 3)
    #pragma unroll
    for (int nc = 0; nc < 2; nc++)
        #pragma unroll
        for (int n8 = 0; n8 < 2; n8++)
            #pragma unroll
            for (int j = 0; j < 2; j++) {
                float s = ls[nc][n8][j], q = lq[nc][n8][j];
                #pragma unroll
                for (int sh = 4; sh <= 16; sh <<= 1) {
                    s += __shfl_xor_sync(0xFFFFFFFFu, s, sh);
                    q += __shfl_xor_sync(0xFFFFFFFFu, q, sh);
                }
                ls[nc][n8][j] = s; lq[nc][n8][j] = q;
            }

    float* sred = (float*)smem;         // reuse stage 0 (all MMA reads done)
    __syncthreads();
    if (tid < 128) sred[tid] = 0.f;
    __syncthreads();
    if ((lane >> 2) == 0) {             // lanes 0..3 per warp
        #pragma unroll
        for (int nc = 0; nc < 2; nc++)
            #pragma unroll
            for (int n8 = 0; n8 < 2; n8++)
                #pragma unroll
                for (int j = 0; j < 2; j++) {
                    const int col = cb + nc * 16 + n8 * 8 + j;
                    atomicAdd(&sred[col],      ls[nc][n8][j]);
                    atomicAdd(&sred[64 + col], lq[nc][n8][j]);
                }
    }
    __syncthreads();
    if (tid < 128) atomicAdd(&g_stats[tid], sred[tid]);
}

// ----------------------------------------------------------------------------
// Kernel 3: apply BN + ReLU, 4 float4 outputs per thread (ILP=4), exact grid.
// Per-block recompute of scale/shift from g_stats.
// ----------------------------------------------------------------------------
__global__ void apply_kernel(const float* __restrict__ gamma,
                             const float* __restrict__ beta,
                             float* __restrict__ out) {
    __shared__ float ssc[64], ssh[64];
    const int t = threadIdx.x;
    if (t < 64) {
        float mean = g_stats[t] * (1.f / (float)NPTS);
        float var  = g_stats[64 + t] * (1.f / (float)NPTS) - mean * mean;
        float sc   = gamma[t] * rsqrtf(var + EPSV);
        ssc[t] = sc;
        ssh[t] = beta[t] - mean * sc;
    }
    __syncthreads();

    const int base = blockIdx.x * 1024 + t;      // float4 output index
    uint2 hv[4];
    #pragma unroll
    for (int j = 0; j < 4; j++)                  // 4 independent 8B loads
        hv[j] = ((const uint2*)g_convh)[base + j * 256];
    #pragma unroll
    for (int j = 0; j < 4; j++) {
        const int i = base + j * 256;
        float2 f0 = __half22float2(*(__half2*)&hv[j].x);
        float2 f1 = __half22float2(*(__half2*)&hv[j].y);
        const int c0 = (i & 15) * 4;
        float4 r;
        r.x = fmaxf(fmaf(f0.x, ssc[c0],     ssh[c0]),     0.f);
        r.y = fmaxf(fmaf(f0.y, ssc[c0 + 1], ssh[c0 + 1]), 0.f);
        r.z = fmaxf(fmaf(f1.x, ssc[c0 + 2], ssh[c0 + 2]), 0.f);
        r.w = fmaxf(fmaf(f1.y, ssc[c0 + 3], ssh[c0 + 3]), 0.f);
        ((float4*)out)[i] = r;
    }
}

// ----------------------------------------------------------------------------
// Launch
// ----------------------------------------------------------------------------
extern "C" void kernel_launch(void* const* d_in, const int* in_sizes, int n_in,
                              void* d_out, int out_size) {
    const float* feat  = (const float*)d_in[0];
    const int*   nbr   = (const int*)d_in[1];
    const float* w     = (const float*)d_in[2];
    const float* gamma = (const float*)d_in[3];
    const float* beta  = (const float*)d_in[4];
    float*       out   = (float*)d_out;
    (void)in_sizes; (void)n_in; (void)out_size;

    cudaFuncSetAttribute(conv_kernel,
                         cudaFuncAttributeMaxDynamicSharedMemorySize, CONV_SMEM);

    prep_kernel<<<FEAT_BLOCKS + KOFF + 1, 256>>>(feat, w);
    conv_kernel<<<NTILES, 256, CONV_SMEM>>>(nbr);
    apply_kernel<<<(NPTS * COUT / 4) / 1024, 256>>>(gamma, beta, out);
}

// round 13
// speedup vs baseline: 3.6567x; 1.0402x over previous
#include <cuda_runtime.h>
#include <cuda_fp16.h>
#include <cstdint>

// ----------------------------------------------------------------------------
// Problem constants
// ----------------------------------------------------------------------------
#define NPTS   262144
#define KOFF   27
#define CIN    64
#define COUT   64
#define TILE_M 128
#define NTILES (NPTS / TILE_M)   // 2048
#define EPSV   1e-5f

// ----------------------------------------------------------------------------
// Device scratch (static allocations only)
// ----------------------------------------------------------------------------
// Features as fp16, 128B per row; extra zero row at index NPTS.
__device__ __half g_feat[(size_t)(NPTS + 1) * 64];
// Weights, transposed: [k][co][ci] fp16
__device__ __half g_wt[(size_t)KOFF * COUT * CIN];
__device__ __half g_convh[(size_t)NPTS * COUT];  // conv output (fp16 scratch)
__device__ float  g_stats[128];                  // [0:64) sum [64:128) sumsq

// ----------------------------------------------------------------------------
// Helpers
// ----------------------------------------------------------------------------
__device__ __forceinline__ uint32_t smem_u32(const void* p) {
    uint32_t a;
    asm("{ .reg .u64 t; cvta.to.shared.u64 t, %1; cvt.u32.u64 %0, t; }"
        : "=r"(a) : "l"(p));
    return a;
}

__device__ __forceinline__ void ldsm4(uint32_t* r, uint32_t addr) {
    asm volatile("ldmatrix.sync.aligned.m8n8.x4.shared.b16 {%0,%1,%2,%3}, [%4];"
                 : "=r"(r[0]), "=r"(r[1]), "=r"(r[2]), "=r"(r[3]) : "r"(addr));
}

__device__ __forceinline__ void mma16816(float* c, const uint32_t* a,
                                         uint32_t b0, uint32_t b1) {
    asm volatile(
        "mma.sync.aligned.m16n8k16.row.col.f32.f16.f16.f32 "
        "{%0,%1,%2,%3}, {%4,%5,%6,%7}, {%8,%9}, {%0,%1,%2,%3};"
        : "+f"(c[0]), "+f"(c[1]), "+f"(c[2]), "+f"(c[3])
        : "r"(a[0]), "r"(a[1]), "r"(a[2]), "r"(a[3]), "r"(b0), "r"(b1));
}

__device__ __forceinline__ void cp16(uint32_t smem_dst, const void* gsrc) {
    asm volatile("cp.async.cg.shared.global [%0], [%1], 16;"
                 :: "r"(smem_dst), "l"(gsrc));
}

// ----------------------------------------------------------------------------
// Kernel 1 (fused prep):
//  - features -> fp16 table: exact grid, 2 groups/thread (4 independent
//    LDG.128, ~22 regs, high occupancy)
//  - weights -> [k][co][ci] fp16 via padded smem transpose (coalesced R+W)
//  - stats -> 0, pad row -> 0
// ----------------------------------------------------------------------------
#define FEAT_BLOCKS  4096      // NPTS*8 groups / (256 thr * 2 groups)

__global__ void prep_kernel(const float* __restrict__ feat,
                            const float* __restrict__ w) {
    const int b = blockIdx.x;
    if (b < FEAT_BLOCKS) {
        const int base = b * 512 + threadIdx.x;
        float4 v[2][2];
        #pragma unroll
        for (int j = 0; j < 2; j++) {               // 4 independent LDG.128
            int g = base + j * 256;
            v[j][0] = ((const float4*)feat)[g * 2];
            v[j][1] = ((const float4*)feat)[g * 2 + 1];
        }
        #pragma unroll
        for (int j = 0; j < 2; j++) {
            int g = base + j * 256;
            uint4 o;
            ((__half2*)&o)[0] = __floats2half2_rn(v[j][0].x, v[j][0].y);
            ((__half2*)&o)[1] = __floats2half2_rn(v[j][0].z, v[j][0].w);
            ((__half2*)&o)[2] = __floats2half2_rn(v[j][1].x, v[j][1].y);
            ((__half2*)&o)[3] = __floats2half2_rn(v[j][1].z, v[j][1].w);
            *(uint4*)(g_feat + (size_t)g * 8) = o;
        }
    } else if (b < FEAT_BLOCKS + KOFF) {
        const int k = b - FEAT_BLOCKS;
        __shared__ __half sw[CIN * 65];             // [ci][co], pad 65
        const float* wk = w + (size_t)k * CIN * COUT;
        #pragma unroll
        for (int j = 0; j < 16; j++) {              // 4096 elements, coalesced
            int idx = threadIdx.x + j * 256;        // ci = idx/64, co = idx%64
            sw[(idx >> 6) * 65 + (idx & 63)] = __float2half_rn(wk[idx]);
        }
        __syncthreads();
        __half* wo = g_wt + (size_t)k * COUT * CIN;
        #pragma unroll
        for (int j = 0; j < 16; j++) {              // out idx: co = /64, ci = %64
            int idx = threadIdx.x + j * 256;
            int co = idx >> 6, ci = idx & 63;
            wo[idx] = sw[ci * 65 + co];             // coalesced 2B writes
        }
    } else {
        if (threadIdx.x < 128) g_stats[threadIdx.x] = 0.f;
        if (threadIdx.x < 8) {                      // zero the pad row (128B)
            uint4 z = make_uint4(0u, 0u, 0u, 0u);
            *(uint4*)(g_feat + (size_t)NPTS * 64 + threadIdx.x * 8) = z;
        }
    }
}

// ----------------------------------------------------------------------------
// Kernel 2: 3-stage cp.async pipeline, 3 CTAs/SM.
// 2048 CTAs x 256 threads (8 warps, warp grid 4M x 2N, 32x32 per warp).
// Stage (24KB): A[128][128B] | W[64][128B], XOR-quad swizzle.
// Iter k: wait fill(k) -> barrier (retires MMA(k-1)) -> issue fill(k+2)
// (targets MMA(k-1)'s buffer: safe) -> MMA(k).
// ----------------------------------------------------------------------------
#define STAGE    24576
#define W_OFF    16384
#define NSTAGE   3
#define CONV_SMEM (NSTAGE * STAGE)

__device__ __forceinline__ void fill_stage(uint32_t buf, int g, int k,
                                           int tid) {
    // A: thread covers row tid>>1, half tid&1 (4 x int4 = 64B)
    const int row  = tid >> 1;
    const int half = tid & 1;
    const uint32_t key = (uint32_t)(row & 7);
    const int4* fr = (const int4*)g_feat + (size_t)g * 8 + half * 4;
    #pragma unroll
    for (int q = 0; q < 4; q++) {
        uint32_t qq = (uint32_t)(half * 4 + q);
        cp16(buf + (uint32_t)row * 128 + ((qq ^ key) << 4), fr + q);
    }
    // W: 512 int4, 2 per thread
    const int4* wsrc = (const int4*)(g_wt + (size_t)k * COUT * CIN);
    #pragma unroll
    for (int j = 0; j < 2; j++) {
        int lin = tid + j * 256;
        int rr = lin >> 3, q = lin & 7;
        cp16(buf + W_OFF + rr * 128 + (((uint32_t)q ^ (uint32_t)(rr & 7)) << 4),
             wsrc + lin);
    }
    asm volatile("cp.async.commit_group;");
}

__global__ void __launch_bounds__(256, 3) conv_kernel(const int* __restrict__ nbr) {
    extern __shared__ char smem[];
    const uint32_t sb  = smem_u32(smem);
    const int tid  = threadIdx.x;
    const int wid  = tid >> 5;
    const int lane = tid & 31;
    const int wm   = wid >> 1;          // 0..3 -> m base wm*32
    const int wn   = wid & 1;           // n base wn*32
    const int row0 = blockIdx.x * TILE_M;

    float c[2][2][2][4];                // [mt][nc][n8][frag]
    #pragma unroll
    for (int a = 0; a < 2; a++)
        #pragma unroll
        for (int b = 0; b < 2; b++)
            #pragma unroll
            for (int d = 0; d < 2; d++)
                #pragma unroll
                for (int j = 0; j < 4; j++) c[a][b][d][j] = 0.f;

    const int* idxp = nbr + row0 + (tid >> 1);  // this thread's gather row

    // --- prologue: fill stages for k = 0,1 ---
    {
        int g0 = __ldg(idxp);
        int g1 = __ldg(idxp + NPTS);
        fill_stage(sb,         g0, 0, tid);
        fill_stage(sb + STAGE, g1, 1, tid);
    }
    int g_next = __ldg(idxp + (size_t)2 * NPTS);   // idx for k=2

    // ldmatrix invariants
    const uint32_t arow  = (uint32_t)(wm * 32 + (lane & 15));
    const uint32_t aswz  = (uint32_t)((lane & 15) & 7);
    const uint32_t ahalf = (uint32_t)(lane >> 4);
    const uint32_t brow  = (uint32_t)(wn * 32 + (lane & 7) + ((lane >> 4) << 3));
    const uint32_t bswz  = (uint32_t)(lane & 7);
    const uint32_t bhalf = (uint32_t)((lane >> 3) & 1);

    int cur = 0;                        // k % 3
    int nxt2 = 2;                       // (k+2) % 3
    for (int k = 0; k < KOFF; k++) {
        // fill(k) done (per-thread), then barrier: visibility + retire MMA(k-1)
        if (k < KOFF - 1) asm volatile("cp.async.wait_group 1;");
        else              asm volatile("cp.async.wait_group 0;");
        __syncthreads();

        if (k + 2 < KOFF) {
            fill_stage(sb + (uint32_t)nxt2 * STAGE, g_next, k + 2, tid);
            if (k + 3 < KOFF) g_next = __ldg(idxp + (size_t)(k + 3) * NPTS);
        }

        const uint32_t A0 = sb + (uint32_t)cur * STAGE;
        const uint32_t WH = A0 + W_OFF;

        #pragma unroll
        for (int ks = 0; ks < 4; ks++) {
            const uint32_t aoff = (((uint32_t)(2 * ks) + ahalf) ^ aswz) << 4;
            uint32_t ah[2][4];
            #pragma unroll
            for (int mt = 0; mt < 2; mt++)
                ldsm4(ah[mt], A0 + (arow + mt * 16) * 128 + aoff);
            const uint32_t boff = (((uint32_t)(2 * ks) + bhalf) ^ bswz) << 4;
            #pragma unroll
            for (int nc = 0; nc < 2; nc++) {
                uint32_t bh[4];
                ldsm4(bh, WH + (brow + nc * 16) * 128 + boff);
                #pragma unroll
                for (int mt = 0; mt < 2; mt++) {
                    mma16816(c[mt][nc][0], ah[mt], bh[0], bh[1]);
                    mma16816(c[mt][nc][1], ah[mt], bh[2], bh[3]);
                }
            }
        }
        cur  = (cur  == 2) ? 0 : cur + 1;
        nxt2 = (nxt2 == 2) ? 0 : nxt2 + 1;
        // no trailing barrier: next iteration's barrier retires these MMAs
    }

    // --- epilogue: write 128x64 fp16 tile + per-channel partial stats ---
    const int r0 = row0 + wm * 32 + (lane >> 2);
    const int cb = wn * 32 + (lane & 3) * 2;
    float ls[2][2][2], lq[2][2][2];     // [nc][n8][j] sums / sumsqs
    #pragma unroll
    for (int nc = 0; nc < 2; nc++)
        #pragma unroll
        for (int n8 = 0; n8 < 2; n8++)
            #pragma unroll
            for (int j = 0; j < 2; j++) { ls[nc][n8][j] = 0.f; lq[nc][n8][j] = 0.f; }

    #pragma unroll
    for (int mt = 0; mt < 2; mt++) {
        const int r = r0 + mt * 16;
        #pragma unroll
        for (int nc = 0; nc < 2; nc++) {
            #pragma unroll
            for (int n8 = 0; n8 < 2; n8++) {
                const int col = cb + nc * 16 + n8 * 8;
                float v0 = c[mt][nc][n8][0], v1 = c[mt][nc][n8][1];
                float v2 = c[mt][nc][n8][2], v3 = c[mt][nc][n8][3];
                *(__half2*)(g_convh + (size_t)r * COUT + col) =
                    __floats2half2_rn(v0, v1);
                *(__half2*)(g_convh + (size_t)(r + 8) * COUT + col) =
                    __floats2half2_rn(v2, v3);
                ls[nc][n8][0] += v0 + v2;  lq[nc][n8][0] += v0 * v0 + v2 * v2;
                ls[nc][n8][1] += v1 + v3;  lq[nc][n8][1] += v1 * v1 + v3 * v3;
            }
        }
    }

    // reduce across the 8 lanes sharing (lane & 3)
    #pragma unroll
    for (int nc = 0; nc < 2; nc++)
        #pragma unroll
        for (int n8 = 0; n8 < 2; n8++)
            #pragma unroll
            for (int j = 0; j < 2; j++) {
                float s = ls[nc][n8][j], q = lq[nc][n8][j];
                #pragma unroll
                for (int sh = 4; sh <= 16; sh <<= 1) {
                    s += __shfl_xor_sync(0xFFFFFFFFu, s, sh);
                    q += __shfl_xor_sync(0xFFFFFFFFu, q, sh);
                }
                ls[nc][n8][j] = s; lq[nc][n8][j] = q;
            }

    float* sred = (float*)smem;         // reuse stage 0 (all MMA reads done)
    __syncthreads();
    if (tid < 128) sred[tid] = 0.f;
    __syncthreads();
    if ((lane >> 2) == 0) {             // lanes 0..3 per warp
        #pragma unroll
        for (int nc = 0; nc < 2; nc++)
            #pragma unroll
            for (int n8 = 0; n8 < 2; n8++)
                #pragma unroll
                for (int j = 0; j < 2; j++) {
                    const int col = cb + nc * 16 + n8 * 8 + j;
                    atomicAdd(&sred[col],      ls[nc][n8][j]);
                    atomicAdd(&sred[64 + col], lq[nc][n8][j]);
                }
    }
    __syncthreads();
    if (tid < 128) atomicAdd(&g_stats[tid], sred[tid]);
}

// ----------------------------------------------------------------------------
// Kernel 3: apply BN + ReLU, 4 float4 outputs per thread (ILP=4), exact grid.
// Per-block recompute of scale/shift from g_stats.
// ----------------------------------------------------------------------------
__global__ void apply_kernel(const float* __restrict__ gamma,
                             const float* __restrict__ beta,
                             float* __restrict__ out) {
    __shared__ float ssc[64], ssh[64];
    const int t = threadIdx.x;
    if (t < 64) {
        float mean = g_stats[t] * (1.f / (float)NPTS);
        float var  = g_stats[64 + t] * (1.f / (float)NPTS) - mean * mean;
        float sc   = gamma[t] * rsqrtf(var + EPSV);
        ssc[t] = sc;
        ssh[t] = beta[t] - mean * sc;
    }
    __syncthreads();

    const int base = blockIdx.x * 1024 + t;      // float4 output index
    uint2 hv[4];
    #pragma unroll
    for (int j = 0; j < 4; j++)                  // 4 independent 8B loads
        hv[j] = ((const uint2*)g_convh)[base + j * 256];
    #pragma unroll
    for (int j = 0; j < 4; j++) {
        const int i = base + j * 256;
        float2 f0 = __half22float2(*(__half2*)&hv[j].x);
        float2 f1 = __half22float2(*(__half2*)&hv[j].y);
        const int c0 = (i & 15) * 4;
        float4 r;
        r.x = fmaxf(fmaf(f0.x, ssc[c0],     ssh[c0]),     0.f);
        r.y = fmaxf(fmaf(f0.y, ssc[c0 + 1], ssh[c0 + 1]), 0.f);
        r.z = fmaxf(fmaf(f1.x, ssc[c0 + 2], ssh[c0 + 2]), 0.f);
        r.w = fmaxf(fmaf(f1.y, ssc[c0 + 3], ssh[c0 + 3]), 0.f);
        ((float4*)out)[i] = r;
    }
}

// ----------------------------------------------------------------------------
// Launch
// ----------------------------------------------------------------------------
extern "C" void kernel_launch(void* const* d_in, const int* in_sizes, int n_in,
                              void* d_out, int out_size) {
    const float* feat  = (const float*)d_in[0];
    const int*   nbr   = (const int*)d_in[1];
    const float* w     = (const float*)d_in[2];
    const float* gamma = (const float*)d_in[3];
    const float* beta  = (const float*)d_in[4];
    float*       out   = (float*)d_out;
    (void)in_sizes; (void)n_in; (void)out_size;

    cudaFuncSetAttribute(conv_kernel,
                         cudaFuncAttributeMaxDynamicSharedMemorySize, CONV_SMEM);

    prep_kernel<<<FEAT_BLOCKS + KOFF + 1, 256>>>(feat, w);
    conv_kernel<<<NTILES, 256, CONV_SMEM>>>(nbr);
    apply_kernel<<<(NPTS * COUT / 4) / 1024, 256>>>(gamma, beta, out);
}

// round 14
// speedup vs baseline: 3.7433x; 1.0237x over previous
#include <cuda_runtime.h>
#include <cuda_fp16.h>
#include <cstdint>

// ----------------------------------------------------------------------------
// Problem constants
// ----------------------------------------------------------------------------
#define NPTS   262144
#define KOFF   27
#define CIN    64
#define COUT   64
#define TILE_M 128
#define NTILES (NPTS / TILE_M)   // 2048
#define EPSV   1e-5f

// ----------------------------------------------------------------------------
// Device scratch (static allocations only)
// ----------------------------------------------------------------------------
// Features as fp16, 128B per row; extra zero row at index NPTS.
__device__ __half g_feat[(size_t)(NPTS + 1) * 64];
// Weights in mma-fragment-major layout:
//   uint4 index = ((k*4 + wn2)*4 + ks)*32 + lane  (= k*512 + lin)
//   lane's uint4 = { B[co0][ci0,ci0+1], B[co0][ci0+8,+9],
//                    B[co0+8][ci0,+1],  B[co0+8][ci0+8,+9] }  as half2s
//   with co0 = wn2*16 + lane/4, ci0 = ks*16 + (lane%4)*2   (B[co][ci] = W^T)
__device__ uint4  g_wtf[(size_t)KOFF * 512];
__device__ __half g_convh[(size_t)NPTS * COUT];  // conv output (fp16 scratch)
__device__ float  g_stats[128];                  // [0:64) sum [64:128) sumsq

// ----------------------------------------------------------------------------
// Helpers
// ----------------------------------------------------------------------------
__device__ __forceinline__ uint32_t smem_u32(const void* p) {
    uint32_t a;
    asm("{ .reg .u64 t; cvta.to.shared.u64 t, %1; cvt.u32.u64 %0, t; }"
        : "=r"(a) : "l"(p));
    return a;
}

__device__ __forceinline__ void ldsm4(uint32_t* r, uint32_t addr) {
    asm volatile("ldmatrix.sync.aligned.m8n8.x4.shared.b16 {%0,%1,%2,%3}, [%4];"
                 : "=r"(r[0]), "=r"(r[1]), "=r"(r[2]), "=r"(r[3]) : "r"(addr));
}

__device__ __forceinline__ void mma16816(float* c, const uint32_t* a,
                                         uint32_t b0, uint32_t b1) {
    asm volatile(
        "mma.sync.aligned.m16n8k16.row.col.f32.f16.f16.f32 "
        "{%0,%1,%2,%3}, {%4,%5,%6,%7}, {%8,%9}, {%0,%1,%2,%3};"
        : "+f"(c[0]), "+f"(c[1]), "+f"(c[2]), "+f"(c[3])
        : "r"(a[0]), "r"(a[1]), "r"(a[2]), "r"(a[3]), "r"(b0), "r"(b1));
}

__device__ __forceinline__ void cp16(uint32_t smem_dst, const void* gsrc) {
    asm volatile("cp.async.cg.shared.global [%0], [%1], 16;"
                 :: "r"(smem_dst), "l"(gsrc));
}

// ----------------------------------------------------------------------------
// Kernel 1 (fused prep):
//  - features -> fp16 table (exact grid, 2 groups/thread)
//  - weights -> fragment-major g_wtf
//  - stats -> 0, pad row -> 0
// ----------------------------------------------------------------------------
#define FEAT_BLOCKS  4096      // NPTS*8 groups / (256 thr * 2 groups)

__global__ void prep_kernel(const float* __restrict__ feat,
                            const float* __restrict__ w) {
    const int b = blockIdx.x;
    if (b < FEAT_BLOCKS) {
        const int base = b * 512 + threadIdx.x;
        float4 v[2][2];
        #pragma unroll
        for (int j = 0; j < 2; j++) {               // 4 independent LDG.128
            int g = base + j * 256;
            v[j][0] = ((const float4*)feat)[g * 2];
            v[j][1] = ((const float4*)feat)[g * 2 + 1];
        }
        #pragma unroll
        for (int j = 0; j < 2; j++) {
            int g = base + j * 256;
            uint4 o;
            ((__half2*)&o)[0] = __floats2half2_rn(v[j][0].x, v[j][0].y);
            ((__half2*)&o)[1] = __floats2half2_rn(v[j][0].z, v[j][0].w);
            ((__half2*)&o)[2] = __floats2half2_rn(v[j][1].x, v[j][1].y);
            ((__half2*)&o)[3] = __floats2half2_rn(v[j][1].z, v[j][1].w);
            *(uint4*)(g_feat + (size_t)g * 8) = o;
        }
    } else if (b < FEAT_BLOCKS + KOFF) {
        const int k = b - FEAT_BLOCKS;
        const float* wk = w + (size_t)k * CIN * COUT;   // wk[ci*64 + co]
        #pragma unroll
        for (int j = 0; j < 2; j++) {
            int lin = threadIdx.x + j * 256;            // 0..511
            int wn2 = lin >> 7;                         // 0..3
            int ks  = (lin >> 5) & 3;                   // 0..3
            int L   = lin & 31;                         // lane
            int co0 = wn2 * 16 + (L >> 2);
            int ci0 = ks * 16 + (L & 3) * 2;
            uint4 o;
            ((__half2*)&o)[0] = __floats2half2_rn(wk[ci0 * 64 + co0],
                                                  wk[(ci0 + 1) * 64 + co0]);
            ((__half2*)&o)[1] = __floats2half2_rn(wk[(ci0 + 8) * 64 + co0],
                                                  wk[(ci0 + 9) * 64 + co0]);
            ((__half2*)&o)[2] = __floats2half2_rn(wk[ci0 * 64 + co0 + 8],
                                                  wk[(ci0 + 1) * 64 + co0 + 8]);
            ((__half2*)&o)[3] = __floats2half2_rn(wk[(ci0 + 8) * 64 + co0 + 8],
                                                  wk[(ci0 + 9) * 64 + co0 + 8]);
            g_wtf[(size_t)k * 512 + lin] = o;
        }
    } else {
        if (threadIdx.x < 128) g_stats[threadIdx.x] = 0.f;
        if (threadIdx.x < 8) {                      // zero the pad row (128B)
            uint4 z = make_uint4(0u, 0u, 0u, 0u);
            *(uint4*)(g_feat + (size_t)NPTS * 64 + threadIdx.x * 8) = z;
        }
    }
}

// ----------------------------------------------------------------------------
// Kernel 2: 4-stage cp.async pipeline (A only), 3 CTAs/SM; W via direct
// fragment LDG.128 from L2, double-buffered across ks.
// 2048 CTAs x 256 threads (8 warps, warp grid 4M x 2N, 32x32 per warp).
// Stage (16KB): A[128][128B], XOR-quad swizzle.
// Iter k: wait fill(k) -> barrier (retires MMA(k-1)) -> issue fill(k+3)
// (targets MMA(k-1)'s buffer: safe) -> MMA(k).
// ----------------------------------------------------------------------------
#define STAGE    16384
#define NSTAGE   4
#define CONV_SMEM (NSTAGE * STAGE)

__device__ __forceinline__ void fill_stage(uint32_t buf, int g, int tid) {
    // A: thread covers row tid>>1, half tid&1 (4 x int4 = 64B)
    const int row  = tid >> 1;
    const int half = tid & 1;
    const uint32_t key = (uint32_t)(row & 7);
    const int4* fr = (const int4*)g_feat + (size_t)g * 8 + half * 4;
    #pragma unroll
    for (int q = 0; q < 4; q++) {
        uint32_t qq = (uint32_t)(half * 4 + q);
        cp16(buf + (uint32_t)row * 128 + ((qq ^ key) << 4), fr + q);
    }
    asm volatile("cp.async.commit_group;");
}

__global__ void __launch_bounds__(256, 3) conv_kernel(const int* __restrict__ nbr) {
    extern __shared__ char smem[];
    const uint32_t sb  = smem_u32(smem);
    const int tid  = threadIdx.x;
    const int wid  = tid >> 5;
    const int lane = tid & 31;
    const int wm   = wid >> 1;          // 0..3 -> m base wm*32
    const int wn   = wid & 1;           // n base wn*32
    const int row0 = blockIdx.x * TILE_M;

    float c[2][2][2][4];                // [mt][nc][n8][frag]
    #pragma unroll
    for (int a = 0; a < 2; a++)
        #pragma unroll
        for (int b = 0; b < 2; b++)
            #pragma unroll
            for (int d = 0; d < 2; d++)
                #pragma unroll
                for (int j = 0; j < 4; j++) c[a][b][d][j] = 0.f;

    const int* idxp = nbr + row0 + (tid >> 1);  // this thread's gather row

    // W fragment base for this warp: [k][wn2=wn*2+nc][ks][lane]
    const uint4* wf = g_wtf + (size_t)(wn * 2) * 128 + lane;
    // offsets: +nc*128, +ks*32, +k*512

    // --- prologue: fill stages for k = 0,1,2; preload W(k=0, ks=0) ---
    {
        int g0 = __ldg(idxp);
        int g1 = __ldg(idxp + NPTS);
        int g2 = __ldg(idxp + 2 * NPTS);
        fill_stage(sb,             g0, tid);
        fill_stage(sb + STAGE,     g1, tid);
        fill_stage(sb + 2 * STAGE, g2, tid);
    }
    int g_next = __ldg(idxp + (size_t)3 * NPTS);   // idx for k=3

    uint4 wb[2][2];                     // [buf][nc] W fragments
    wb[0][0] = __ldg(wf);
    wb[0][1] = __ldg(wf + 128);

    // ldmatrix invariants (A side)
    const uint32_t arow  = (uint32_t)(wm * 32 + (lane & 15));
    const uint32_t aswz  = (uint32_t)((lane & 15) & 7);
    const uint32_t ahalf = (uint32_t)(lane >> 4);

    for (int k = 0; k < KOFF; k++) {
        // fill(k) done (per-thread), then barrier: visibility + retire MMA(k-1)
        if (k < KOFF - 2)       asm volatile("cp.async.wait_group 2;");
        else if (k == KOFF - 2) asm volatile("cp.async.wait_group 1;");
        else                    asm volatile("cp.async.wait_group 0;");
        __syncthreads();

        if (k + 3 < KOFF) {
            fill_stage(sb + (uint32_t)((k + 3) & 3) * STAGE, g_next, tid);
            if (k + 4 < KOFF) g_next = __ldg(idxp + (size_t)(k + 4) * NPTS);
        }

        const uint32_t A0 = sb + (uint32_t)(k & 3) * STAGE;

        #pragma unroll
        for (int ks = 0; ks < 4; ks++) {
            const int cb_ = ks & 1, nb_ = (ks + 1) & 1;
            // prefetch next ks (or next k's ks=0) while mma runs
            if (ks < 3) {
                const uint4* p = wf + (size_t)k * 512 + (ks + 1) * 32;
                wb[nb_][0] = __ldg(p);
                wb[nb_][1] = __ldg(p + 128);
            } else if (k + 1 < KOFF) {
                const uint4* p = wf + (size_t)(k + 1) * 512;
                wb[nb_][0] = __ldg(p);
                wb[nb_][1] = __ldg(p + 128);
            }

            const uint32_t aoff = (((uint32_t)(2 * ks) + ahalf) ^ aswz) << 4;
            uint32_t ah[2][4];
            #pragma unroll
            for (int mt = 0; mt < 2; mt++)
                ldsm4(ah[mt], A0 + (arow + mt * 16) * 128 + aoff);

            #pragma unroll
            for (int nc = 0; nc < 2; nc++) {
                const uint32_t b0 = wb[cb_][nc].x, b1 = wb[cb_][nc].y;
                const uint32_t b2 = wb[cb_][nc].z, b3 = wb[cb_][nc].w;
                #pragma unroll
                for (int mt = 0; mt < 2; mt++) {
                    mma16816(c[mt][nc][0], ah[mt], b0, b1);
                    mma16816(c[mt][nc][1], ah[mt], b2, b3);
                }
            }
        }
        // no trailing barrier: next iteration's barrier retires these MMAs
    }

    // --- epilogue: write 128x64 fp16 tile + per-channel partial stats ---
    const int r0 = row0 + wm * 32 + (lane >> 2);
    const int cb = wn * 32 + (lane & 3) * 2;
    float ls[2][2][2], lq[2][2][2];     // [nc][n8][j] sums / sumsqs
    #pragma unroll
    for (int nc = 0; nc < 2; nc++)
        #pragma unroll
        for (int n8 = 0; n8 < 2; n8++)
            #pragma unroll
            for (int j = 0; j < 2; j++) { ls[nc][n8][j] = 0.f; lq[nc][n8][j] = 0.f; }

    #pragma unroll
    for (int mt = 0; mt < 2; mt++) {
        const int r = r0 + mt * 16;
        #pragma unroll
        for (int nc = 0; nc < 2; nc++) {
            #pragma unroll
            for (int n8 = 0; n8 < 2; n8++) {
                const int col = cb + nc * 16 + n8 * 8;
                float v0 = c[mt][nc][n8][0], v1 = c[mt][nc][n8][1];
                float v2 = c[mt][nc][n8][2], v3 = c[mt][nc][n8][3];
                *(__half2*)(g_convh + (size_t)r * COUT + col) =
                    __floats2half2_rn(v0, v1);
                *(__half2*)(g_convh + (size_t)(r + 8) * COUT + col) =
                    __floats2half2_rn(v2, v3);
                ls[nc][n8][0] += v0 + v2;  lq[nc][n8][0] += v0 * v0 + v2 * v2;
                ls[nc][n8][1] += v1 + v3;  lq[nc][n8][1] += v1 * v1 + v3 * v3;
            }
        }
    }

    // reduce across the 8 lanes sharing (lane & 3)
    #pragma unroll
    for (int nc = 0; nc < 2; nc++)
        #pragma unroll
        for (int n8 = 0; n8 < 2; n8++)
            #pragma unroll
            for (int j = 0; j < 2; j++) {
                float s = ls[nc][n8][j], q = lq[nc][n8][j];
                #pragma unroll
                for (int sh = 4; sh <= 16; sh <<= 1) {
                    s += __shfl_xor_sync(0xFFFFFFFFu, s, sh);
                    q += __shfl_xor_sync(0xFFFFFFFFu, q, sh);
                }
                ls[nc][n8][j] = s; lq[nc][n8][j] = q;
            }

    float* sred = (float*)smem;         // reuse stage 0 (all MMA reads done)
    __syncthreads();
    if (tid < 128) sred[tid] = 0.f;
    __syncthreads();
    if ((lane >> 2) == 0) {             // lanes 0..3 per warp
        #pragma unroll
        for (int nc = 0; nc < 2; nc++)
            #pragma unroll
            for (int n8 = 0; n8 < 2; n8++)
                #pragma unroll
                for (int j = 0; j < 2; j++) {
                    const int col = cb + nc * 16 + n8 * 8 + j;
                    atomicAdd(&sred[col],      ls[nc][n8][j]);
                    atomicAdd(&sred[64 + col], lq[nc][n8][j]);
                }
    }
    __syncthreads();
    if (tid < 128) atomicAdd(&g_stats[tid], sred[tid]);
}

// ----------------------------------------------------------------------------
// Kernel 3: apply BN + ReLU, 4 float4 outputs per thread (ILP=4), exact grid.
// Per-block recompute of scale/shift from g_stats.
// ----------------------------------------------------------------------------
__global__ void apply_kernel(const float* __restrict__ gamma,
                             const float* __restrict__ beta,
                             float* __restrict__ out) {
    __shared__ float ssc[64], ssh[64];
    const int t = threadIdx.x;
    if (t < 64) {
        float mean = g_stats[t] * (1.f / (float)NPTS);
        float var  = g_stats[64 + t] * (1.f / (float)NPTS) - mean * mean;
        float sc   = gamma[t] * rsqrtf(var + EPSV);
        ssc[t] = sc;
        ssh[t] = beta[t] - mean * sc;
    }
    __syncthreads();

    const int base = blockIdx.x * 1024 + t;      // float4 output index
    uint2 hv[4];
    #pragma unroll
    for (int j = 0; j < 4; j++)                  // 4 independent 8B loads
        hv[j] = ((const uint2*)g_convh)[base + j * 256];
    #pragma unroll
    for (int j = 0; j < 4; j++) {
        const int i = base + j * 256;
        float2 f0 = __half22float2(*(__half2*)&hv[j].x);
        float2 f1 = __half22float2(*(__half2*)&hv[j].y);
        const int c0 = (i & 15) * 4;
        float4 r;
        r.x = fmaxf(fmaf(f0.x, ssc[c0],     ssh[c0]),     0.f);
        r.y = fmaxf(fmaf(f0.y, ssc[c0 + 1], ssh[c0 + 1]), 0.f);
        r.z = fmaxf(fmaf(f1.x, ssc[c0 + 2], ssh[c0 + 2]), 0.f);
        r.w = fmaxf(fmaf(f1.y, ssc[c0 + 3], ssh[c0 + 3]), 0.f);
        ((float4*)out)[i] = r;
    }
}

// ----------------------------------------------------------------------------
// Launch
// ----------------------------------------------------------------------------
extern "C" void kernel_launch(void* const* d_in, const int* in_sizes, int n_in,
                              void* d_out, int out_size) {
    const float* feat  = (const float*)d_in[0];
    const int*   nbr   = (const int*)d_in[1];
    const float* w     = (const float*)d_in[2];
    const float* gamma = (const float*)d_in[3];
    const float* beta  = (const float*)d_in[4];
    float*       out   = (float*)d_out;
    (void)in_sizes; (void)n_in; (void)out_size;

    cudaFuncSetAttribute(conv_kernel,
                         cudaFuncAttributeMaxDynamicSharedMemorySize, CONV_SMEM);

    prep_kernel<<<FEAT_BLOCKS + KOFF + 1, 256>>>(feat, w);
    conv_kernel<<<NTILES, 256, CONV_SMEM>>>(nbr);
    apply_kernel<<<(NPTS * COUT / 4) / 1024, 256>>>(gamma, beta, out);
}